// round 4
// baseline (speedup 1.0000x reference)
#include <cuda_runtime.h>
#include <math.h>
#include <stdint.h>

#define LSEQ   1024
#define DMODEL 4096
#define NH     32
#define QLORA  1536
#define KVLORA 512
#define ROPED  64
#define NOPED  128
#define VD     128
#define QHD    192
#define IHN    64
#define IHDN   128
#define NTOPK  256

#define ATT_SCALE 0.07216878364870323f   /* 192^-0.5 */
#define IW_SCALE  0.011048543456039806f  /* (64*128)^-0.5 */

/* Correctly-rounded rope trig: replicate JAX's f32 angle, then exact sincos. */
__device__ __forceinline__ void rope_trig(int l, int i, float* sn, float* cs)
{
    double invd = pow(10000.0, -(double)i * (1.0 / 32.0));
    float  invf = (float)invd;
    float  ang  = (float)l * invf;       /* f32 multiply, as in reference */
    double a    = (double)ang;
    *cs = (float)cos(a);
    *sn = (float)sin(a);
}

/* ---------------- scratch (device globals; no allocs allowed) ------------ */
__device__ float g_tmp  [LSEQ * QLORA];
__device__ float g_qr   [LSEQ * QLORA];
__device__ float g_q    [LSEQ * NH * QHD];
__device__ float g_ckv  [LSEQ * (KVLORA + ROPED)];
__device__ float g_kvlat[LSEQ * KVLORA];
__device__ float g_kpe  [LSEQ * ROPED];
__device__ float g_iq   [LSEQ * IHN * IHDN];
__device__ float g_ik   [LSEQ * IHDN];
__device__ float g_iw   [LSEQ * IHN];
__device__ float g_isc  [LSEQ * LSEQ];
__device__ int   g_topk [LSEQ * NTOPK];
__device__ float g_k    [NH * LSEQ * NOPED];
__device__ float g_v    [NH * LSEQ * VD];
__device__ float g_ao   [LSEQ * NH * VD];

/* ---------------- generic tiled GEMM: C = A * B(^T), optional batch ------ */
/* A: [M,K] row-major. TB=true: B is [N,K] (C=A*B^T). TB=false: B is [K,N]. */
/* ACC = float (fast path) or double (exact path for topk-feeding tensors). */
template <bool TB, typename ACC>
__global__ void __launch_bounds__(256)
gemm_kernel(const float* __restrict__ A, const float* __restrict__ B,
            float* __restrict__ C, int M, int N, int K,
            long strideB, long strideC)
{
    __shared__ float As[16][64];
    __shared__ float Bs[16][64];

    const float* Bp = B + (long)blockIdx.z * strideB;
    float*       Cp = C + (long)blockIdx.z * strideC;

    const int bm  = blockIdx.y * 64;
    const int bn  = blockIdx.x * 64;
    const int tid = threadIdx.x;
    const int tm  = tid >> 4;
    const int tn  = tid & 15;

    const int ra = tid >> 2;
    const int ca = (tid & 3) << 2;
    const int rb = tid >> 4;
    const int cb = (tid & 15) << 2;

    ACC acc[4][4];
#pragma unroll
    for (int i = 0; i < 4; i++)
#pragma unroll
        for (int j = 0; j < 4; j++) acc[i][j] = (ACC)0;

    for (int k0 = 0; k0 < K; k0 += 16) {
        float4 va = *(const float4*)(A + (long)(bm + ra) * K + k0 + ca);
        As[ca + 0][ra] = va.x; As[ca + 1][ra] = va.y;
        As[ca + 2][ra] = va.z; As[ca + 3][ra] = va.w;

        if (TB) {
            float4 vb = *(const float4*)(Bp + (long)(bn + ra) * K + k0 + ca);
            Bs[ca + 0][ra] = vb.x; Bs[ca + 1][ra] = vb.y;
            Bs[ca + 2][ra] = vb.z; Bs[ca + 3][ra] = vb.w;
        } else {
            float4 vb = *(const float4*)(Bp + (long)(k0 + rb) * N + bn + cb);
            *(float4*)&Bs[rb][cb] = vb;
        }
        __syncthreads();

#pragma unroll
        for (int kk = 0; kk < 16; kk++) {
            float4 a4 = *(const float4*)&As[kk][tm << 2];
            float4 b4 = *(const float4*)&Bs[kk][tn << 2];
            ACC av[4] = {(ACC)a4.x, (ACC)a4.y, (ACC)a4.z, (ACC)a4.w};
            ACC bv[4] = {(ACC)b4.x, (ACC)b4.y, (ACC)b4.z, (ACC)b4.w};
#pragma unroll
            for (int i = 0; i < 4; i++)
#pragma unroll
                for (int j = 0; j < 4; j++)
                    acc[i][j] += av[i] * bv[j];
        }
        __syncthreads();
    }

#pragma unroll
    for (int i = 0; i < 4; i++) {
        float4 r;
        r.x = (float)acc[i][0]; r.y = (float)acc[i][1];
        r.z = (float)acc[i][2]; r.w = (float)acc[i][3];
        *(float4*)(Cp + (long)(bm + (tm << 2) + i) * N + bn + (tn << 2)) = r;
    }
}

/* ---------------- rmsnorm over a row (double-precision stats) ---------- */
__global__ void rmsnorm_kernel(const float* __restrict__ in,
                               const float* __restrict__ w,
                               float* __restrict__ out,
                               int cols, int inStride, int outStride, float eps)
{
    const int l = blockIdx.x;
    const int t = threadIdx.x;
    __shared__ double red[8];
    __shared__ float rshared;

    double ss = 0.0;
    for (int c = t; c < cols; c += 256) {
        double v = (double)in[(long)l * inStride + c];
        ss += v * v;
    }
#pragma unroll
    for (int o = 16; o; o >>= 1) ss += __shfl_xor_sync(0xffffffffu, ss, o);
    if ((t & 31) == 0) red[t >> 5] = ss;
    __syncthreads();
    if (t == 0) {
        double s = 0.0;
        for (int i = 0; i < 8; i++) s += red[i];
        rshared = (float)rsqrt(s / (double)cols + (double)eps);
    }
    __syncthreads();
    float r = rshared;
    for (int c = t; c < cols; c += 256)
        out[(long)l * outStride + c] = in[(long)l * inStride + c] * r * w[c];
}

/* ---------------- layernorm (in-place) on g_ik, cols=128, fp64 stats --- */
__global__ void layernorm_ik_kernel(const float* __restrict__ w,
                                    const float* __restrict__ b)
{
    const int l = blockIdx.x;
    const int t = threadIdx.x;           /* 128 threads */
    __shared__ double red[4];
    __shared__ double stat;

    float v = g_ik[l * IHDN + t];

    double s = (double)v;
#pragma unroll
    for (int o = 16; o; o >>= 1) s += __shfl_xor_sync(0xffffffffu, s, o);
    if ((t & 31) == 0) red[t >> 5] = s;
    __syncthreads();
    if (t == 0) stat = (red[0] + red[1] + red[2] + red[3]) * (1.0 / 128.0);
    __syncthreads();
    double mu = stat;
    double d  = (double)v - mu;

    double s2 = d * d;
#pragma unroll
    for (int o = 16; o; o >>= 1) s2 += __shfl_xor_sync(0xffffffffu, s2, o);
    __syncthreads();
    if ((t & 31) == 0) red[t >> 5] = s2;
    __syncthreads();
    if (t == 0) stat = (red[0] + red[1] + red[2] + red[3]) * (1.0 / 128.0);
    __syncthreads();
    double var = stat;

    g_ik[l * IHDN + t] = (float)(d * rsqrt(var + 1e-5)) * w[t] + b[t];
}

/* ---------------- traditional rope (in-place), pairs 2i/2i+1 ----------- */
/* rotation arithmetic in strict f32 mul/sub/add (no FMA contraction)     */
__global__ void rope_inplace_kernel(float* data, int rowStride,
                                    int chunkStride, int off)
{
    const int l = blockIdx.x;
    const int c = blockIdx.y;
    const int i = threadIdx.x;           /* 32 pairs (d=64) */
    float* p = data + (long)l * rowStride + c * chunkStride + off + 2 * i;
    float sn, cs;
    rope_trig(l, i, &sn, &cs);
    float x1 = p[0], x2 = p[1];
    p[0] = __fsub_rn(__fmul_rn(x1, cs), __fmul_rn(x2, sn));
    p[1] = __fadd_rn(__fmul_rn(x1, sn), __fmul_rn(x2, cs));
}

/* ---------------- k_pe = rope(ckv[:,512:576]) -------------------------- */
__global__ void kpe_kernel()
{
    const int l = blockIdx.x;
    const int i = threadIdx.x;           /* 32 pairs */
    const float* src = g_ckv + (long)l * (KVLORA + ROPED) + KVLORA + 2 * i;
    float sn, cs;
    rope_trig(l, i, &sn, &cs);
    float x1 = src[0], x2 = src[1];
    g_kpe[l * ROPED + 2 * i]     = __fsub_rn(__fmul_rn(x1, cs), __fmul_rn(x2, sn));
    g_kpe[l * ROPED + 2 * i + 1] = __fadd_rn(__fmul_rn(x1, sn), __fmul_rn(x2, cs));
}

/* ---------------- indexer scores (fp64): S[l][s] = sum_h relu(.)*iw ---- */
__global__ void __launch_bounds__(256) indexer_kernel()
{
    const int bs = blockIdx.x;
    const int bl = blockIdx.y;
    if (bs > bl) return;
    const int s0 = bs * 64;
    const int l0 = bl * 64;

    __shared__ float iqs[64][64];
    __shared__ float iks[64][64];

    const int tid = threadIdx.x;
    const int tm  = tid >> 4;
    const int tn  = tid & 15;

    double acc[4][4];
#pragma unroll
    for (int i = 0; i < 4; i++)
#pragma unroll
        for (int j = 0; j < 4; j++) acc[i][j] = 0.0;

    for (int h = 0; h < IHN; h++) {
        double dot[4][4];
#pragma unroll
        for (int i = 0; i < 4; i++)
#pragma unroll
            for (int j = 0; j < 4; j++) dot[i][j] = 0.0;

        for (int dc = 0; dc < IHDN; dc += 64) {
            __syncthreads();
#pragma unroll
            for (int t4 = 0; t4 < 4; t4++) {
                int id4 = tid + t4 * 256;
                int row = id4 >> 4;
                int c4  = (id4 & 15) << 2;
                float4 v = *(const float4*)(g_iq + (long)(l0 + row) * (IHN * IHDN)
                                            + h * IHDN + dc + c4);
                iqs[c4 + 0][row] = v.x; iqs[c4 + 1][row] = v.y;
                iqs[c4 + 2][row] = v.z; iqs[c4 + 3][row] = v.w;
                float4 u = *(const float4*)(g_ik + (long)(s0 + row) * IHDN + dc + c4);
                iks[c4 + 0][row] = u.x; iks[c4 + 1][row] = u.y;
                iks[c4 + 2][row] = u.z; iks[c4 + 3][row] = u.w;
            }
            __syncthreads();

#pragma unroll 8
            for (int kk = 0; kk < 64; kk++) {
                float4 a4 = *(const float4*)&iqs[kk][tm << 2];
                float4 b4 = *(const float4*)&iks[kk][tn << 2];
                double av[4] = {(double)a4.x, (double)a4.y, (double)a4.z, (double)a4.w};
                double bv[4] = {(double)b4.x, (double)b4.y, (double)b4.z, (double)b4.w};
#pragma unroll
                for (int i = 0; i < 4; i++)
#pragma unroll
                    for (int j = 0; j < 4; j++)
                        dot[i][j] += av[i] * bv[j];
            }
        }

#pragma unroll
        for (int i = 0; i < 4; i++) {
            /* reference: iw_f32 * scale_f32, rounded f32, then weighted sum */
            float wf = __fmul_rn(g_iw[(l0 + (tm << 2) + i) * IHN + h], IW_SCALE);
            double w = (double)wf;
#pragma unroll
            for (int j = 0; j < 4; j++) {
                double r = dot[i][j] > 0.0 ? dot[i][j] : 0.0;
                acc[i][j] += r * w;
            }
        }
    }

#pragma unroll
    for (int i = 0; i < 4; i++)
#pragma unroll
        for (int j = 0; j < 4; j++)
            g_isc[(long)(l0 + (tm << 2) + i) * LSEQ + s0 + (tn << 2) + j] =
                (float)acc[i][j];
}

/* ---------------- per-row top-256: stable bitonic (ties -> low index) -- */
__global__ void __launch_bounds__(1024) topk_kernel()
{
    const int l = blockIdx.x;
    const int t = threadIdx.x;
    __shared__ float sv[1024];
    __shared__ int   si[1024];

    sv[t] = (t <= l) ? g_isc[(long)l * LSEQ + t] : -INFINITY;
    si[t] = t;
    __syncthreads();

    for (int k = 2; k <= 1024; k <<= 1) {
        for (int j = k >> 1; j > 0; j >>= 1) {
            int p = t ^ j;
            if (p > t) {
                bool desc = ((t & k) == 0);
                float vt = sv[t], vp = sv[p];
                int   it = si[t], ip = si[p];
                /* priority: higher value first; tie -> lower index first */
                bool t_lower = (vt < vp) || (vt == vp && it > ip);
                bool sw = desc ? t_lower : !t_lower;
                if (sw) {
                    sv[t] = vp; sv[p] = vt;
                    si[t] = ip; si[p] = it;
                }
            }
            __syncthreads();
        }
    }
    if (t < NTOPK) g_topk[l * NTOPK + t] = si[t];
}

/* ---------------- sparse attention over selected keys ------------------ */
__global__ void __launch_bounds__(128) attn_kernel()
{
    const int l = blockIdx.x;
    const int h = blockIdx.y;
    const int t = threadIdx.x;           /* 128 threads */
    __shared__ float q[QHD];
    __shared__ int   sidx[NTOPK];
    __shared__ float sc[NTOPK];
    __shared__ float red[4];
    __shared__ float smax, ssum;

    const long qbase = (long)l * (NH * QHD) + h * QHD;
    q[t] = g_q[qbase + t];
    if (t < 64) q[128 + t] = g_q[qbase + 128 + t] * ATT_SCALE;
    sidx[t]       = g_topk[l * NTOPK + t];
    sidx[t + 128] = g_topk[l * NTOPK + t + 128];
    __syncthreads();

    const int warp = t >> 5, lane = t & 31;

    for (int jj = 0; jj < 64; jj++) {
        int j = (warp << 6) + jj;
        int s = sidx[j];
        float r = -INFINITY;
        if (s <= l) {
            const float* kp = g_k + ((long)h * LSEQ + s) * NOPED;
            float dn = q[lane]      * kp[lane]
                     + q[lane + 32] * kp[lane + 32]
                     + q[lane + 64] * kp[lane + 64]
                     + q[lane + 96] * kp[lane + 96];
            const float* pp = g_kpe + s * ROPED;
            float dp = q[128 + lane] * pp[lane]
                     + q[160 + lane] * pp[lane + 32];
            float d = dn * ATT_SCALE + dp;
#pragma unroll
            for (int o = 16; o; o >>= 1) d += __shfl_xor_sync(0xffffffffu, d, o);
            r = d;
        }
        if (lane == 0) sc[j] = r;
    }
    __syncthreads();

    /* softmax */
    float m = fmaxf(sc[t], sc[t + 128]);
#pragma unroll
    for (int o = 16; o; o >>= 1) m = fmaxf(m, __shfl_xor_sync(0xffffffffu, m, o));
    if (lane == 0) red[warp] = m;
    __syncthreads();
    if (t == 0) smax = fmaxf(fmaxf(red[0], red[1]), fmaxf(red[2], red[3]));
    __syncthreads();
    float mx = smax;

    float p0 = expf(sc[t] - mx);
    float p1 = expf(sc[t + 128] - mx);
    float s = p0 + p1;
#pragma unroll
    for (int o = 16; o; o >>= 1) s += __shfl_xor_sync(0xffffffffu, s, o);
    if (lane == 0) red[warp] = s;
    __syncthreads();
    if (t == 0) ssum = red[0] + red[1] + red[2] + red[3];
    __syncthreads();
    float inv = 1.f / ssum;

    sc[t]       = p0 * inv;
    sc[t + 128] = p1 * inv;
    __syncthreads();

    /* output: thread t = output dim */
    float acc = 0.f;
    for (int j = 0; j < NTOPK; j++) {
        float p = sc[j];
        if (p != 0.f)
            acc += p * g_v[((long)h * LSEQ + sidx[j]) * VD + t];
    }
    g_ao[(long)l * (NH * VD) + h * VD + t] = acc;
}

/* ---------------------------- launcher --------------------------------- */
extern "C" void kernel_launch(void* const* d_in, const int* in_sizes, int n_in,
                              void* d_out, int out_size)
{
    (void)in_sizes; (void)n_in; (void)out_size;
    const float* x         = (const float*)d_in[0];
    /* d_in[1] = mask (tril) — recomputed analytically, ignored */
    const float* W_qa      = (const float*)d_in[2];
    const float* qa_ln_w   = (const float*)d_in[3];
    const float* W_qb      = (const float*)d_in[4];
    const float* W_kva     = (const float*)d_in[5];
    const float* kva_ln_w  = (const float*)d_in[6];
    const float* W_eq      = (const float*)d_in[7];
    const float* W_uo      = (const float*)d_in[8];
    const float* W_o       = (const float*)d_in[9];
    const float* idx_wqb   = (const float*)d_in[10];
    const float* idx_wk    = (const float*)d_in[11];
    const float* idx_kln_w = (const float*)d_in[12];
    const float* idx_kln_b = (const float*)d_in[13];
    const float* idx_wproj = (const float*)d_in[14];
    float* out = (float*)d_out;

    float *p_tmp, *p_qr, *p_q, *p_ckv, *p_kvlat, *p_iq, *p_ik, *p_iw, *p_k, *p_v, *p_ao;
    cudaGetSymbolAddress((void**)&p_tmp,   g_tmp);
    cudaGetSymbolAddress((void**)&p_qr,    g_qr);
    cudaGetSymbolAddress((void**)&p_q,     g_q);
    cudaGetSymbolAddress((void**)&p_ckv,   g_ckv);
    cudaGetSymbolAddress((void**)&p_kvlat, g_kvlat);
    cudaGetSymbolAddress((void**)&p_iq,    g_iq);
    cudaGetSymbolAddress((void**)&p_ik,    g_ik);
    cudaGetSymbolAddress((void**)&p_iw,    g_iw);
    cudaGetSymbolAddress((void**)&p_k,     g_k);
    cudaGetSymbolAddress((void**)&p_v,     g_v);
    cudaGetSymbolAddress((void**)&p_ao,    g_ao);

    /* q path (tmp/qr exact: they feed the indexer) */
    gemm_kernel<true, double><<<dim3(QLORA / 64, LSEQ / 64, 1), 256>>>(x, W_qa, p_tmp, LSEQ, QLORA, DMODEL, 0, 0);
    rmsnorm_kernel<<<LSEQ, 256>>>(p_tmp, qa_ln_w, p_qr, QLORA, QLORA, QLORA, 1e-6f);
    gemm_kernel<true, float><<<dim3(NH * QHD / 64, LSEQ / 64, 1), 256>>>(p_qr, W_qb, p_q, LSEQ, NH * QHD, QLORA, 0, 0);
    rope_inplace_kernel<<<dim3(LSEQ, NH), 32>>>(p_q, NH * QHD, QHD, NOPED);

    /* kv path */
    gemm_kernel<true, float><<<dim3((KVLORA + ROPED) / 64, LSEQ / 64, 1), 256>>>(x, W_kva, p_ckv, LSEQ, KVLORA + ROPED, DMODEL, 0, 0);
    rmsnorm_kernel<<<LSEQ, 256>>>(p_ckv, kva_ln_w, p_kvlat, KVLORA, KVLORA + ROPED, KVLORA, 1e-6f);
    kpe_kernel<<<LSEQ, 32>>>();

    /* indexer path (all exact) */
    gemm_kernel<true, double><<<dim3(IHN * IHDN / 64, LSEQ / 64, 1), 256>>>(p_qr, idx_wqb, p_iq, LSEQ, IHN * IHDN, QLORA, 0, 0);
    rope_inplace_kernel<<<dim3(LSEQ, IHN), 32>>>(p_iq, IHN * IHDN, IHDN, 0);
    gemm_kernel<true, double><<<dim3(IHDN / 64, LSEQ / 64, 1), 256>>>(x, idx_wk, p_ik, LSEQ, IHDN, DMODEL, 0, 0);
    layernorm_ik_kernel<<<LSEQ, 128>>>(idx_kln_w, idx_kln_b);
    rope_inplace_kernel<<<dim3(LSEQ, 1), 32>>>(p_ik, IHDN, IHDN, 0);
    gemm_kernel<true, double><<<dim3(IHN / 64, LSEQ / 64, 1), 256>>>(x, idx_wproj, p_iw, LSEQ, IHN, DMODEL, 0, 0);

    indexer_kernel<<<dim3(LSEQ / 64, LSEQ / 64), 256>>>();
    topk_kernel<<<LSEQ, 1024>>>();

    /* k, v expansion (batched over heads) */
    gemm_kernel<false, float><<<dim3(NOPED / 64, LSEQ / 64, NH), 256>>>(p_kvlat, W_eq, p_k, LSEQ, NOPED, KVLORA,
                                                                        (long)KVLORA * NOPED, (long)LSEQ * NOPED);
    gemm_kernel<true, float><<<dim3(VD / 64, LSEQ / 64, NH), 256>>>(p_kvlat, W_uo, p_v, LSEQ, VD, KVLORA,
                                                                    (long)VD * KVLORA, (long)LSEQ * VD);

    /* sparse attention */
    attn_kernel<<<dim3(LSEQ, NH), 128>>>();

    /* output projection */
    gemm_kernel<true, float><<<dim3(DMODEL / 64, LSEQ / 64, 1), 256>>>(p_ao, W_o, out, LSEQ, DMODEL, DMODEL, 0, 0);
}

// round 5
// speedup vs baseline: 13.9767x; 13.9767x over previous
#include <cuda_runtime.h>
#include <math.h>
#include <stdint.h>

#define LSEQ   1024
#define DMODEL 4096
#define NH     32
#define QLORA  1536
#define KVLORA 512
#define ROPED  64
#define NOPED  128
#define VD     128
#define QHD    192
#define IHN    64
#define IHDN   128
#define NTOPK  256

#define ATT_SCALE 0.07216878364870323f   /* 192^-0.5 */
#define IW_SCALE  0.011048543456039806f  /* (64*128)^-0.5 */

/* Correctly-rounded rope trig: replicate JAX's f32 angle, then exact sincos. */
__device__ __forceinline__ void rope_trig(int l, int i, float* sn, float* cs)
{
    double invd = pow(10000.0, -(double)i * (1.0 / 32.0));
    float  invf = (float)invd;
    float  ang  = (float)l * invf;       /* f32 multiply, as in reference */
    double a    = (double)ang;
    *cs = (float)cos(a);
    *sn = (float)sin(a);
}

/* ---------------- scratch (device globals; no allocs allowed) ------------ */
__device__ float g_tmp  [LSEQ * QLORA];
__device__ float g_qr   [LSEQ * QLORA];
__device__ float g_q    [LSEQ * NH * QHD];
__device__ float g_ckv  [LSEQ * (KVLORA + ROPED)];
__device__ float g_kvlat[LSEQ * KVLORA];
__device__ float g_kpe  [LSEQ * ROPED];
__device__ float g_iq   [LSEQ * IHN * IHDN];
__device__ float g_ik   [LSEQ * IHDN];
__device__ float g_iw   [LSEQ * IHN];
__device__ float g_isc  [LSEQ * LSEQ];
__device__ int   g_topk [LSEQ * NTOPK];
__device__ float g_k    [NH * LSEQ * NOPED];
__device__ float g_v    [NH * LSEQ * VD];
__device__ float g_ao   [LSEQ * NH * VD];

/* ---------------- generic tiled GEMM: C = A * B(^T), optional batch ------ */
/* A: [M,K] row-major. TB=true: B is [N,K] (C=A*B^T). TB=false: B is [K,N]. */
/* KAHAN=true: fp32 FMA within 16-wide k-tile, Kahan-compensated cross-tile */
/* accumulation (noise ~2e-7 rel, needed by the topk-feeding score path).   */
template <bool TB, bool KAHAN>
__global__ void __launch_bounds__(256)
gemm_kernel(const float* __restrict__ A, const float* __restrict__ B,
            float* __restrict__ C, int M, int N, int K,
            long strideB, long strideC)
{
    __shared__ float As[16][64];
    __shared__ float Bs[16][64];

    const float* Bp = B + (long)blockIdx.z * strideB;
    float*       Cp = C + (long)blockIdx.z * strideC;

    const int bm  = blockIdx.y * 64;
    const int bn  = blockIdx.x * 64;
    const int tid = threadIdx.x;
    const int tm  = tid >> 4;
    const int tn  = tid & 15;

    const int ra = tid >> 2;
    const int ca = (tid & 3) << 2;
    const int rb = tid >> 4;
    const int cb = (tid & 15) << 2;

    float s_[4][4], c_[4][4];
#pragma unroll
    for (int i = 0; i < 4; i++)
#pragma unroll
        for (int j = 0; j < 4; j++) { s_[i][j] = 0.f; c_[i][j] = 0.f; }

    for (int k0 = 0; k0 < K; k0 += 16) {
        float4 va = *(const float4*)(A + (long)(bm + ra) * K + k0 + ca);
        As[ca + 0][ra] = va.x; As[ca + 1][ra] = va.y;
        As[ca + 2][ra] = va.z; As[ca + 3][ra] = va.w;

        if (TB) {
            float4 vb = *(const float4*)(Bp + (long)(bn + ra) * K + k0 + ca);
            Bs[ca + 0][ra] = vb.x; Bs[ca + 1][ra] = vb.y;
            Bs[ca + 2][ra] = vb.z; Bs[ca + 3][ra] = vb.w;
        } else {
            float4 vb = *(const float4*)(Bp + (long)(k0 + rb) * N + bn + cb);
            *(float4*)&Bs[rb][cb] = vb;
        }
        __syncthreads();

        if (KAHAN) {
            float t_[4][4];
#pragma unroll
            for (int i = 0; i < 4; i++)
#pragma unroll
                for (int j = 0; j < 4; j++) t_[i][j] = 0.f;

#pragma unroll
            for (int kk = 0; kk < 16; kk++) {
                float4 a4 = *(const float4*)&As[kk][tm << 2];
                float4 b4 = *(const float4*)&Bs[kk][tn << 2];
                float av[4] = {a4.x, a4.y, a4.z, a4.w};
                float bv[4] = {b4.x, b4.y, b4.z, b4.w};
#pragma unroll
                for (int i = 0; i < 4; i++)
#pragma unroll
                    for (int j = 0; j < 4; j++)
                        t_[i][j] = __fmaf_rn(av[i], bv[j], t_[i][j]);
            }
            /* Kahan merge of tile partial into (s_, c_) */
#pragma unroll
            for (int i = 0; i < 4; i++)
#pragma unroll
                for (int j = 0; j < 4; j++) {
                    float y = __fsub_rn(t_[i][j], c_[i][j]);
                    float u = __fadd_rn(s_[i][j], y);
                    c_[i][j] = __fsub_rn(__fsub_rn(u, s_[i][j]), y);
                    s_[i][j] = u;
                }
        } else {
#pragma unroll
            for (int kk = 0; kk < 16; kk++) {
                float4 a4 = *(const float4*)&As[kk][tm << 2];
                float4 b4 = *(const float4*)&Bs[kk][tn << 2];
                float av[4] = {a4.x, a4.y, a4.z, a4.w};
                float bv[4] = {b4.x, b4.y, b4.z, b4.w};
#pragma unroll
                for (int i = 0; i < 4; i++)
#pragma unroll
                    for (int j = 0; j < 4; j++)
                        s_[i][j] = __fmaf_rn(av[i], bv[j], s_[i][j]);
            }
        }
        __syncthreads();
    }

#pragma unroll
    for (int i = 0; i < 4; i++) {
        float4 r;
        r.x = s_[i][0]; r.y = s_[i][1]; r.z = s_[i][2]; r.w = s_[i][3];
        *(float4*)(Cp + (long)(bm + (tm << 2) + i) * N + bn + (tn << 2)) = r;
    }
}

/* ---------------- rmsnorm over a row (double-precision stats) ---------- */
__global__ void rmsnorm_kernel(const float* __restrict__ in,
                               const float* __restrict__ w,
                               float* __restrict__ out,
                               int cols, int inStride, int outStride, float eps)
{
    const int l = blockIdx.x;
    const int t = threadIdx.x;
    __shared__ double red[8];
    __shared__ float rshared;

    double ss = 0.0;
    for (int c = t; c < cols; c += 256) {
        double v = (double)in[(long)l * inStride + c];
        ss += v * v;
    }
#pragma unroll
    for (int o = 16; o; o >>= 1) ss += __shfl_xor_sync(0xffffffffu, ss, o);
    if ((t & 31) == 0) red[t >> 5] = ss;
    __syncthreads();
    if (t == 0) {
        double s = 0.0;
        for (int i = 0; i < 8; i++) s += red[i];
        rshared = (float)rsqrt(s / (double)cols + (double)eps);
    }
    __syncthreads();
    float r = rshared;
    for (int c = t; c < cols; c += 256)
        out[(long)l * outStride + c] = in[(long)l * inStride + c] * r * w[c];
}

/* ---------------- layernorm (in-place) on g_ik, cols=128, fp64 stats --- */
__global__ void layernorm_ik_kernel(const float* __restrict__ w,
                                    const float* __restrict__ b)
{
    const int l = blockIdx.x;
    const int t = threadIdx.x;           /* 128 threads */
    __shared__ double red[4];
    __shared__ double stat;

    float v = g_ik[l * IHDN + t];

    double s = (double)v;
#pragma unroll
    for (int o = 16; o; o >>= 1) s += __shfl_xor_sync(0xffffffffu, s, o);
    if ((t & 31) == 0) red[t >> 5] = s;
    __syncthreads();
    if (t == 0) stat = (red[0] + red[1] + red[2] + red[3]) * (1.0 / 128.0);
    __syncthreads();
    double mu = stat;
    double d  = (double)v - mu;

    double s2 = d * d;
#pragma unroll
    for (int o = 16; o; o >>= 1) s2 += __shfl_xor_sync(0xffffffffu, s2, o);
    __syncthreads();
    if ((t & 31) == 0) red[t >> 5] = s2;
    __syncthreads();
    if (t == 0) stat = (red[0] + red[1] + red[2] + red[3]) * (1.0 / 128.0);
    __syncthreads();
    double var = stat;

    g_ik[l * IHDN + t] = (float)(d * rsqrt(var + 1e-5)) * w[t] + b[t];
}

/* ---------------- traditional rope (in-place), pairs 2i/2i+1 ----------- */
__global__ void rope_inplace_kernel(float* data, int rowStride,
                                    int chunkStride, int off)
{
    const int l = blockIdx.x;
    const int c = blockIdx.y;
    const int i = threadIdx.x;           /* 32 pairs (d=64) */
    float* p = data + (long)l * rowStride + c * chunkStride + off + 2 * i;
    float sn, cs;
    rope_trig(l, i, &sn, &cs);
    float x1 = p[0], x2 = p[1];
    p[0] = __fsub_rn(__fmul_rn(x1, cs), __fmul_rn(x2, sn));
    p[1] = __fadd_rn(__fmul_rn(x1, sn), __fmul_rn(x2, cs));
}

/* ---------------- k_pe = rope(ckv[:,512:576]) -------------------------- */
__global__ void kpe_kernel()
{
    const int l = blockIdx.x;
    const int i = threadIdx.x;           /* 32 pairs */
    const float* src = g_ckv + (long)l * (KVLORA + ROPED) + KVLORA + 2 * i;
    float sn, cs;
    rope_trig(l, i, &sn, &cs);
    float x1 = src[0], x2 = src[1];
    g_kpe[l * ROPED + 2 * i]     = __fsub_rn(__fmul_rn(x1, cs), __fmul_rn(x2, sn));
    g_kpe[l * ROPED + 2 * i + 1] = __fadd_rn(__fmul_rn(x1, sn), __fmul_rn(x2, cs));
}

/* ---------------- indexer scores: fp32 Kahan dots + fp64 head-sum ------ */
__global__ void __launch_bounds__(256) indexer_kernel()
{
    const int bs = blockIdx.x;
    const int bl = blockIdx.y;
    if (bs > bl) return;
    const int s0 = bs * 64;
    const int l0 = bl * 64;

    __shared__ float iqs[64][64];
    __shared__ float iks[64][64];

    const int tid = threadIdx.x;
    const int tm  = tid >> 4;
    const int tn  = tid & 15;

    double acc[4][4];
#pragma unroll
    for (int i = 0; i < 4; i++)
#pragma unroll
        for (int j = 0; j < 4; j++) acc[i][j] = 0.0;

    for (int h = 0; h < IHN; h++) {
        float ds[4][4], cc[4][4];
#pragma unroll
        for (int i = 0; i < 4; i++)
#pragma unroll
            for (int j = 0; j < 4; j++) { ds[i][j] = 0.f; cc[i][j] = 0.f; }

        for (int dc = 0; dc < IHDN; dc += 64) {
            __syncthreads();
#pragma unroll
            for (int t4 = 0; t4 < 4; t4++) {
                int id4 = tid + t4 * 256;
                int row = id4 >> 4;
                int c4  = (id4 & 15) << 2;
                float4 v = *(const float4*)(g_iq + (long)(l0 + row) * (IHN * IHDN)
                                            + h * IHDN + dc + c4);
                iqs[c4 + 0][row] = v.x; iqs[c4 + 1][row] = v.y;
                iqs[c4 + 2][row] = v.z; iqs[c4 + 3][row] = v.w;
                float4 u = *(const float4*)(g_ik + (long)(s0 + row) * IHDN + dc + c4);
                iks[c4 + 0][row] = u.x; iks[c4 + 1][row] = u.y;
                iks[c4 + 2][row] = u.z; iks[c4 + 3][row] = u.w;
            }
            __syncthreads();

#pragma unroll
            for (int g = 0; g < 4; g++) {
                float dt[4][4];
#pragma unroll
                for (int i = 0; i < 4; i++)
#pragma unroll
                    for (int j = 0; j < 4; j++) dt[i][j] = 0.f;

#pragma unroll
                for (int kk = g * 16; kk < g * 16 + 16; kk++) {
                    float4 a4 = *(const float4*)&iqs[kk][tm << 2];
                    float4 b4 = *(const float4*)&iks[kk][tn << 2];
                    float av[4] = {a4.x, a4.y, a4.z, a4.w};
                    float bv[4] = {b4.x, b4.y, b4.z, b4.w};
#pragma unroll
                    for (int i = 0; i < 4; i++)
#pragma unroll
                        for (int j = 0; j < 4; j++)
                            dt[i][j] = __fmaf_rn(av[i], bv[j], dt[i][j]);
                }
#pragma unroll
                for (int i = 0; i < 4; i++)
#pragma unroll
                    for (int j = 0; j < 4; j++) {
                        float y = __fsub_rn(dt[i][j], cc[i][j]);
                        float u = __fadd_rn(ds[i][j], y);
                        cc[i][j] = __fsub_rn(__fsub_rn(u, ds[i][j]), y);
                        ds[i][j] = u;
                    }
            }
        }

#pragma unroll
        for (int i = 0; i < 4; i++) {
            float wf = __fmul_rn(g_iw[(l0 + (tm << 2) + i) * IHN + h], IW_SCALE);
            double w = (double)wf;
#pragma unroll
            for (int j = 0; j < 4; j++) {
                double r = (double)ds[i][j];
                r = r > 0.0 ? r : 0.0;
                acc[i][j] += r * w;
            }
        }
    }

#pragma unroll
    for (int i = 0; i < 4; i++)
#pragma unroll
        for (int j = 0; j < 4; j++)
            g_isc[(long)(l0 + (tm << 2) + i) * LSEQ + s0 + (tn << 2) + j] =
                (float)acc[i][j];
}

/* ---------------- per-row top-256: stable bitonic (ties -> low index) -- */
__global__ void __launch_bounds__(1024) topk_kernel()
{
    const int l = blockIdx.x;
    const int t = threadIdx.x;
    __shared__ float sv[1024];
    __shared__ int   si[1024];

    sv[t] = (t <= l) ? g_isc[(long)l * LSEQ + t] : -INFINITY;
    si[t] = t;
    __syncthreads();

    for (int k = 2; k <= 1024; k <<= 1) {
        for (int j = k >> 1; j > 0; j >>= 1) {
            int p = t ^ j;
            if (p > t) {
                bool desc = ((t & k) == 0);
                float vt = sv[t], vp = sv[p];
                int   it = si[t], ip = si[p];
                bool t_lower = (vt < vp) || (vt == vp && it > ip);
                bool sw = desc ? t_lower : !t_lower;
                if (sw) {
                    sv[t] = vp; sv[p] = vt;
                    si[t] = ip; si[p] = it;
                }
            }
            __syncthreads();
        }
    }
    if (t < NTOPK) g_topk[l * NTOPK + t] = si[t];
}

/* ---------------- sparse attention over selected keys ------------------ */
__global__ void __launch_bounds__(128) attn_kernel()
{
    const int l = blockIdx.x;
    const int h = blockIdx.y;
    const int t = threadIdx.x;           /* 128 threads */
    __shared__ float q[QHD];
    __shared__ int   sidx[NTOPK];
    __shared__ float sc[NTOPK];
    __shared__ float red[4];
    __shared__ float smax, ssum;

    const long qbase = (long)l * (NH * QHD) + h * QHD;
    q[t] = g_q[qbase + t];
    if (t < 64) q[128 + t] = g_q[qbase + 128 + t] * ATT_SCALE;
    sidx[t]       = g_topk[l * NTOPK + t];
    sidx[t + 128] = g_topk[l * NTOPK + t + 128];
    __syncthreads();

    const int warp = t >> 5, lane = t & 31;

    for (int jj = 0; jj < 64; jj++) {
        int j = (warp << 6) + jj;
        int s = sidx[j];
        float r = -INFINITY;
        if (s <= l) {
            const float* kp = g_k + ((long)h * LSEQ + s) * NOPED;
            float dn = q[lane]      * kp[lane]
                     + q[lane + 32] * kp[lane + 32]
                     + q[lane + 64] * kp[lane + 64]
                     + q[lane + 96] * kp[lane + 96];
            const float* pp = g_kpe + s * ROPED;
            float dp = q[128 + lane] * pp[lane]
                     + q[160 + lane] * pp[lane + 32];
            float d = dn * ATT_SCALE + dp;
#pragma unroll
            for (int o = 16; o; o >>= 1) d += __shfl_xor_sync(0xffffffffu, d, o);
            r = d;
        }
        if (lane == 0) sc[j] = r;
    }
    __syncthreads();

    /* softmax */
    float m = fmaxf(sc[t], sc[t + 128]);
#pragma unroll
    for (int o = 16; o; o >>= 1) m = fmaxf(m, __shfl_xor_sync(0xffffffffu, m, o));
    if (lane == 0) red[warp] = m;
    __syncthreads();
    if (t == 0) smax = fmaxf(fmaxf(red[0], red[1]), fmaxf(red[2], red[3]));
    __syncthreads();
    float mx = smax;

    float p0 = expf(sc[t] - mx);
    float p1 = expf(sc[t + 128] - mx);
    float s = p0 + p1;
#pragma unroll
    for (int o = 16; o; o >>= 1) s += __shfl_xor_sync(0xffffffffu, s, o);
    if (lane == 0) red[warp] = s;
    __syncthreads();
    if (t == 0) ssum = red[0] + red[1] + red[2] + red[3];
    __syncthreads();
    float inv = 1.f / ssum;

    sc[t]       = p0 * inv;
    sc[t + 128] = p1 * inv;
    __syncthreads();

    /* output: thread t = output dim */
    float acc = 0.f;
    for (int j = 0; j < NTOPK; j++) {
        float p = sc[j];
        if (p != 0.f)
            acc += p * g_v[((long)h * LSEQ + sidx[j]) * VD + t];
    }
    g_ao[(long)l * (NH * VD) + h * VD + t] = acc;
}

/* ---------------------------- launcher --------------------------------- */
extern "C" void kernel_launch(void* const* d_in, const int* in_sizes, int n_in,
                              void* d_out, int out_size)
{
    (void)in_sizes; (void)n_in; (void)out_size;
    const float* x         = (const float*)d_in[0];
    /* d_in[1] = mask (tril) — recomputed analytically, ignored */
    const float* W_qa      = (const float*)d_in[2];
    const float* qa_ln_w   = (const float*)d_in[3];
    const float* W_qb      = (const float*)d_in[4];
    const float* W_kva     = (const float*)d_in[5];
    const float* kva_ln_w  = (const float*)d_in[6];
    const float* W_eq      = (const float*)d_in[7];
    const float* W_uo      = (const float*)d_in[8];
    const float* W_o       = (const float*)d_in[9];
    const float* idx_wqb   = (const float*)d_in[10];
    const float* idx_wk    = (const float*)d_in[11];
    const float* idx_kln_w = (const float*)d_in[12];
    const float* idx_kln_b = (const float*)d_in[13];
    const float* idx_wproj = (const float*)d_in[14];
    float* out = (float*)d_out;

    float *p_tmp, *p_qr, *p_q, *p_ckv, *p_kvlat, *p_iq, *p_ik, *p_iw, *p_k, *p_v, *p_ao;
    cudaGetSymbolAddress((void**)&p_tmp,   g_tmp);
    cudaGetSymbolAddress((void**)&p_qr,    g_qr);
    cudaGetSymbolAddress((void**)&p_q,     g_q);
    cudaGetSymbolAddress((void**)&p_ckv,   g_ckv);
    cudaGetSymbolAddress((void**)&p_kvlat, g_kvlat);
    cudaGetSymbolAddress((void**)&p_iq,    g_iq);
    cudaGetSymbolAddress((void**)&p_ik,    g_ik);
    cudaGetSymbolAddress((void**)&p_iw,    g_iw);
    cudaGetSymbolAddress((void**)&p_k,     g_k);
    cudaGetSymbolAddress((void**)&p_v,     g_v);
    cudaGetSymbolAddress((void**)&p_ao,    g_ao);

    /* q path (tmp/qr feed the indexer -> Kahan) */
    gemm_kernel<true, true ><<<dim3(QLORA / 64, LSEQ / 64, 1), 256>>>(x, W_qa, p_tmp, LSEQ, QLORA, DMODEL, 0, 0);
    rmsnorm_kernel<<<LSEQ, 256>>>(p_tmp, qa_ln_w, p_qr, QLORA, QLORA, QLORA, 1e-6f);
    gemm_kernel<true, false><<<dim3(NH * QHD / 64, LSEQ / 64, 1), 256>>>(p_qr, W_qb, p_q, LSEQ, NH * QHD, QLORA, 0, 0);
    rope_inplace_kernel<<<dim3(LSEQ, NH), 32>>>(p_q, NH * QHD, QHD, NOPED);

    /* kv path */
    gemm_kernel<true, false><<<dim3((KVLORA + ROPED) / 64, LSEQ / 64, 1), 256>>>(x, W_kva, p_ckv, LSEQ, KVLORA + ROPED, DMODEL, 0, 0);
    rmsnorm_kernel<<<LSEQ, 256>>>(p_ckv, kva_ln_w, p_kvlat, KVLORA, KVLORA + ROPED, KVLORA, 1e-6f);
    kpe_kernel<<<LSEQ, 32>>>();

    /* indexer path (score-exact -> Kahan) */
    gemm_kernel<true, true ><<<dim3(IHN * IHDN / 64, LSEQ / 64, 1), 256>>>(p_qr, idx_wqb, p_iq, LSEQ, IHN * IHDN, QLORA, 0, 0);
    rope_inplace_kernel<<<dim3(LSEQ, IHN), 32>>>(p_iq, IHN * IHDN, IHDN, 0);
    gemm_kernel<true, true ><<<dim3(IHDN / 64, LSEQ / 64, 1), 256>>>(x, idx_wk, p_ik, LSEQ, IHDN, DMODEL, 0, 0);
    layernorm_ik_kernel<<<LSEQ, 128>>>(idx_kln_w, idx_kln_b);
    rope_inplace_kernel<<<dim3(LSEQ, 1), 32>>>(p_ik, IHDN, IHDN, 0);
    gemm_kernel<true, true ><<<dim3(IHN / 64, LSEQ / 64, 1), 256>>>(x, idx_wproj, p_iw, LSEQ, IHN, DMODEL, 0, 0);

    indexer_kernel<<<dim3(LSEQ / 64, LSEQ / 64), 256>>>();
    topk_kernel<<<LSEQ, 1024>>>();

    /* k, v expansion (batched over heads) */
    gemm_kernel<false, false><<<dim3(NOPED / 64, LSEQ / 64, NH), 256>>>(p_kvlat, W_eq, p_k, LSEQ, NOPED, KVLORA,
                                                                        (long)KVLORA * NOPED, (long)LSEQ * NOPED);
    gemm_kernel<true, false><<<dim3(VD / 64, LSEQ / 64, NH), 256>>>(p_kvlat, W_uo, p_v, LSEQ, VD, KVLORA,
                                                                    (long)VD * KVLORA, (long)LSEQ * VD);

    /* sparse attention */
    attn_kernel<<<dim3(LSEQ, NH), 128>>>();

    /* output projection */
    gemm_kernel<true, false><<<dim3(DMODEL / 64, LSEQ / 64, 1), 256>>>(p_ao, W_o, out, LSEQ, DMODEL, DMODEL, 0, 0);
}

// round 6
// speedup vs baseline: 19.0853x; 1.3655x over previous
#include <cuda_runtime.h>
#include <math.h>
#include <stdint.h>

#define LSEQ   1024
#define DMODEL 4096
#define NH     32
#define QLORA  1536
#define KVLORA 512
#define ROPED  64
#define NOPED  128
#define VD     128
#define QHD    192
#define IHN    64
#define IHDN   128
#define NTOPK  256

#define ATT_SCALE 0.07216878364870323f   /* 192^-0.5 */
#define IW_SCALE  0.011048543456039806f  /* (64*128)^-0.5 */

__device__ __forceinline__ uint32_t tf32bits(float x)
{
    uint32_t u;
    asm("cvt.rna.tf32.f32 %0, %1;" : "=r"(u) : "f"(x));
    return u;
}

/* Correctly-rounded rope trig: replicate JAX's f32 angle, then exact sincos. */
__device__ __forceinline__ void rope_trig(int l, int i, float* sn, float* cs)
{
    double invd = pow(10000.0, -(double)i * (1.0 / 32.0));
    float  invf = (float)invd;
    float  ang  = (float)l * invf;       /* f32 multiply, as in reference */
    double a    = (double)ang;
    *cs = (float)cos(a);
    *sn = (float)sin(a);
}

/* ---------------- scratch (device globals; no allocs allowed) ------------ */
__device__ float  g_tmp  [LSEQ * QLORA];
__device__ float  g_qr   [LSEQ * QLORA];
__device__ float  g_q    [LSEQ * NH * QHD];
__device__ float  g_ckv  [LSEQ * (KVLORA + ROPED)];
__device__ float  g_kvlat[LSEQ * KVLORA];
__device__ float  g_kpe  [LSEQ * ROPED];
__device__ float  g_iq   [LSEQ * IHN * IHDN];
__device__ float  g_ik   [LSEQ * IHDN];
__device__ float  g_iw   [LSEQ * IHN];
__device__ float  g_isc  [LSEQ * LSEQ];
__device__ int    g_topk [LSEQ * NTOPK];
__device__ float  g_k    [NH * LSEQ * NOPED];
__device__ float  g_v    [NH * LSEQ * VD];
__device__ float  g_ao   [LSEQ * NH * VD];
__device__ float2 g_rope [LSEQ * 32];

/* ================== TF32 tensor-core GEMM (non-score path) =============== */
/* C = A * B(^T). A: [M,K]. TB=true: B [N,K]; TB=false: B [K,N].            */
/* 128x128 block tile, k-step 32, 8 warps (m64 x n32 warp tiles).           */
#define TCPAD 4
template <bool TB>
__global__ void __launch_bounds__(256)
gemm_tc(const float* __restrict__ A, const float* __restrict__ B,
        float* __restrict__ C, int M, int N, int K,
        long strideB, long strideC)
{
    __shared__ uint32_t As[128][32 + TCPAD];
    __shared__ uint32_t Bs[128][32 + TCPAD];

    const float* Bp = B + (long)blockIdx.z * strideB;
    float*       Cp = C + (long)blockIdx.z * strideC;

    const int bm   = blockIdx.y * 128;
    const int bn   = blockIdx.x * 128;
    const int tid  = threadIdx.x;
    const int wid  = tid >> 5;
    const int lane = tid & 31;
    const int g    = lane >> 2;      /* groupID 0..7 */
    const int t4   = lane & 3;       /* thread-in-group */

    const int wm = (wid & 1) * 64;   /* warp row offset in tile */
    const int wn = (wid >> 1) * 32;  /* warp col offset in tile */

    float acc[4][4][4];
#pragma unroll
    for (int mi = 0; mi < 4; mi++)
#pragma unroll
        for (int ni = 0; ni < 4; ni++)
#pragma unroll
            for (int r = 0; r < 4; r++) acc[mi][ni][r] = 0.f;

    const int lr = tid >> 1;            /* 0..127 */
    const int lc = (tid & 1) * 16;      /* 0 or 16 */

    for (int k0 = 0; k0 < K; k0 += 32) {
        /* A tile: rows always valid (M multiple of 128) */
#pragma unroll
        for (int q = 0; q < 4; q++) {
            float4 v = *(const float4*)(A + (long)(bm + lr) * K + k0 + lc + q * 4);
            *(uint4*)&As[lr][lc + q * 4] =
                make_uint4(tf32bits(v.x), tf32bits(v.y), tf32bits(v.z), tf32bits(v.w));
        }
        if (TB) {
            int row = bn + lr;
            if (row < N) {
#pragma unroll
                for (int q = 0; q < 4; q++) {
                    float4 v = *(const float4*)(Bp + (long)row * K + k0 + lc + q * 4);
                    *(uint4*)&Bs[lr][lc + q * 4] =
                        make_uint4(tf32bits(v.x), tf32bits(v.y), tf32bits(v.z), tf32bits(v.w));
                }
            } else {
#pragma unroll
                for (int q = 0; q < 4; q++)
                    *(uint4*)&Bs[lr][lc + q * 4] = make_uint4(0, 0, 0, 0);
            }
        } else {
            /* B [K,N]: transpose into Bs[n][k] */
            int k  = tid >> 3;              /* 0..31 */
            int nb = (tid & 7) * 16;        /* 0..112 */
#pragma unroll
            for (int q = 0; q < 16; q += 4) {
                int n = bn + nb + q;
                if (n + 3 < N) {
                    float4 v = *(const float4*)(Bp + (long)(k0 + k) * N + n);
                    Bs[nb + q + 0][k] = tf32bits(v.x);
                    Bs[nb + q + 1][k] = tf32bits(v.y);
                    Bs[nb + q + 2][k] = tf32bits(v.z);
                    Bs[nb + q + 3][k] = tf32bits(v.w);
                } else {
#pragma unroll
                    for (int e = 0; e < 4; e++) {
                        float f = (n + e < N) ? Bp[(long)(k0 + k) * N + n + e] : 0.f;
                        Bs[nb + q + e][k] = tf32bits(f);
                    }
                }
            }
        }
        __syncthreads();

#pragma unroll
        for (int ks = 0; ks < 4; ks++) {
            const int kb = ks * 8;
            uint32_t af[4][4];
#pragma unroll
            for (int mi = 0; mi < 4; mi++) {
                int r = wm + mi * 16;
                af[mi][0] = As[r + g][kb + t4];
                af[mi][1] = As[r + g + 8][kb + t4];
                af[mi][2] = As[r + g][kb + t4 + 4];
                af[mi][3] = As[r + g + 8][kb + t4 + 4];
            }
            uint32_t bf[4][2];
#pragma unroll
            for (int ni = 0; ni < 4; ni++) {
                int c = wn + ni * 8;
                bf[ni][0] = Bs[c + g][kb + t4];
                bf[ni][1] = Bs[c + g][kb + t4 + 4];
            }
#pragma unroll
            for (int mi = 0; mi < 4; mi++)
#pragma unroll
                for (int ni = 0; ni < 4; ni++) {
                    asm volatile(
                        "mma.sync.aligned.m16n8k8.row.col.f32.tf32.tf32.f32 "
                        "{%0,%1,%2,%3}, {%4,%5,%6,%7}, {%8,%9}, {%0,%1,%2,%3};\n"
                        : "+f"(acc[mi][ni][0]), "+f"(acc[mi][ni][1]),
                          "+f"(acc[mi][ni][2]), "+f"(acc[mi][ni][3])
                        : "r"(af[mi][0]), "r"(af[mi][1]),
                          "r"(af[mi][2]), "r"(af[mi][3]),
                          "r"(bf[ni][0]), "r"(bf[ni][1]));
                }
        }
        __syncthreads();
    }

#pragma unroll
    for (int mi = 0; mi < 4; mi++) {
#pragma unroll
        for (int ni = 0; ni < 4; ni++) {
            int r0 = bm + wm + mi * 16 + g;
            int c0 = bn + wn + ni * 8 + t4 * 2;
            if (c0 < N) {
                Cp[(long)r0 * N + c0] = acc[mi][ni][0];
                if (c0 + 1 < N) Cp[(long)r0 * N + c0 + 1] = acc[mi][ni][1];
                Cp[(long)(r0 + 8) * N + c0] = acc[mi][ni][2];
                if (c0 + 1 < N) Cp[(long)(r0 + 8) * N + c0 + 1] = acc[mi][ni][3];
            }
        }
    }
}

/* ============ scalar Kahan GEMM (score path, exact) ====================== */
template <bool TB>
__global__ void __launch_bounds__(256)
gemm_kahan(const float* __restrict__ A, const float* __restrict__ B,
           float* __restrict__ C, int M, int N, int K)
{
    __shared__ float As[16][64];
    __shared__ float Bs[16][64];

    const int bm  = blockIdx.y * 64;
    const int bn  = blockIdx.x * 64;
    const int tid = threadIdx.x;
    const int tm  = tid >> 4;
    const int tn  = tid & 15;

    const int ra = tid >> 2;
    const int ca = (tid & 3) << 2;
    const int rb = tid >> 4;
    const int cb = (tid & 15) << 2;

    float s_[4][4], c_[4][4];
#pragma unroll
    for (int i = 0; i < 4; i++)
#pragma unroll
        for (int j = 0; j < 4; j++) { s_[i][j] = 0.f; c_[i][j] = 0.f; }

    for (int k0 = 0; k0 < K; k0 += 16) {
        float4 va = *(const float4*)(A + (long)(bm + ra) * K + k0 + ca);
        As[ca + 0][ra] = va.x; As[ca + 1][ra] = va.y;
        As[ca + 2][ra] = va.z; As[ca + 3][ra] = va.w;

        if (TB) {
            float4 vb = *(const float4*)(B + (long)(bn + ra) * K + k0 + ca);
            Bs[ca + 0][ra] = vb.x; Bs[ca + 1][ra] = vb.y;
            Bs[ca + 2][ra] = vb.z; Bs[ca + 3][ra] = vb.w;
        } else {
            float4 vb = *(const float4*)(B + (long)(k0 + rb) * N + bn + cb);
            *(float4*)&Bs[rb][cb] = vb;
        }
        __syncthreads();

        float t_[4][4];
#pragma unroll
        for (int i = 0; i < 4; i++)
#pragma unroll
            for (int j = 0; j < 4; j++) t_[i][j] = 0.f;

#pragma unroll
        for (int kk = 0; kk < 16; kk++) {
            float4 a4 = *(const float4*)&As[kk][tm << 2];
            float4 b4 = *(const float4*)&Bs[kk][tn << 2];
            float av[4] = {a4.x, a4.y, a4.z, a4.w};
            float bv[4] = {b4.x, b4.y, b4.z, b4.w};
#pragma unroll
            for (int i = 0; i < 4; i++)
#pragma unroll
                for (int j = 0; j < 4; j++)
                    t_[i][j] = __fmaf_rn(av[i], bv[j], t_[i][j]);
        }
#pragma unroll
        for (int i = 0; i < 4; i++)
#pragma unroll
            for (int j = 0; j < 4; j++) {
                float y = __fsub_rn(t_[i][j], c_[i][j]);
                float u = __fadd_rn(s_[i][j], y);
                c_[i][j] = __fsub_rn(__fsub_rn(u, s_[i][j]), y);
                s_[i][j] = u;
            }
        __syncthreads();
    }

#pragma unroll
    for (int i = 0; i < 4; i++) {
        float4 r;
        r.x = s_[i][0]; r.y = s_[i][1]; r.z = s_[i][2]; r.w = s_[i][3];
        *(float4*)(C + (long)(bm + (tm << 2) + i) * N + bn + (tn << 2)) = r;
    }
}

/* ---------------- rmsnorm over a row (double-precision stats) ---------- */
__global__ void rmsnorm_kernel(const float* __restrict__ in,
                               const float* __restrict__ w,
                               float* __restrict__ out,
                               int cols, int inStride, int outStride, float eps)
{
    const int l = blockIdx.x;
    const int t = threadIdx.x;
    __shared__ double red[8];
    __shared__ float rshared;

    double ss = 0.0;
    for (int c = t; c < cols; c += 256) {
        double v = (double)in[(long)l * inStride + c];
        ss += v * v;
    }
#pragma unroll
    for (int o = 16; o; o >>= 1) ss += __shfl_xor_sync(0xffffffffu, ss, o);
    if ((t & 31) == 0) red[t >> 5] = ss;
    __syncthreads();
    if (t == 0) {
        double s = 0.0;
        for (int i = 0; i < 8; i++) s += red[i];
        rshared = (float)rsqrt(s / (double)cols + (double)eps);
    }
    __syncthreads();
    float r = rshared;
    for (int c = t; c < cols; c += 256)
        out[(long)l * outStride + c] = in[(long)l * inStride + c] * r * w[c];
}

/* ---------------- layernorm (in-place) on g_ik, cols=128, fp64 stats --- */
__global__ void layernorm_ik_kernel(const float* __restrict__ w,
                                    const float* __restrict__ b)
{
    const int l = blockIdx.x;
    const int t = threadIdx.x;           /* 128 threads */
    __shared__ double red[4];
    __shared__ double stat;

    float v = g_ik[l * IHDN + t];

    double s = (double)v;
#pragma unroll
    for (int o = 16; o; o >>= 1) s += __shfl_xor_sync(0xffffffffu, s, o);
    if ((t & 31) == 0) red[t >> 5] = s;
    __syncthreads();
    if (t == 0) stat = (red[0] + red[1] + red[2] + red[3]) * (1.0 / 128.0);
    __syncthreads();
    double mu = stat;
    double d  = (double)v - mu;

    double s2 = d * d;
#pragma unroll
    for (int o = 16; o; o >>= 1) s2 += __shfl_xor_sync(0xffffffffu, s2, o);
    __syncthreads();
    if ((t & 31) == 0) red[t >> 5] = s2;
    __syncthreads();
    if (t == 0) stat = (red[0] + red[1] + red[2] + red[3]) * (1.0 / 128.0);
    __syncthreads();
    double var = stat;

    g_ik[l * IHDN + t] = (float)(d * rsqrt(var + 1e-5)) * w[t] + b[t];
}

/* ---------------- rope table (exact trig, computed once) --------------- */
__global__ void rope_table_kernel()
{
    const int l = blockIdx.x;
    const int i = threadIdx.x;           /* 32 */
    float sn, cs;
    rope_trig(l, i, &sn, &cs);
    g_rope[l * 32 + i] = make_float2(sn, cs);
}

/* ---------------- rope application (table lookup) ---------------------- */
__global__ void rope_apply_kernel(float* data, int rowStride,
                                  int chunkStride, int off, int nchunks)
{
    const int l = blockIdx.x;
    const int c = blockIdx.y * blockDim.y + threadIdx.y;
    if (c >= nchunks) return;
    const int i = threadIdx.x;
    float2 sc = g_rope[l * 32 + i];
    float* p = data + (long)l * rowStride + c * chunkStride + off + 2 * i;
    float x1 = p[0], x2 = p[1];
    p[0] = __fsub_rn(__fmul_rn(x1, sc.y), __fmul_rn(x2, sc.x));
    p[1] = __fadd_rn(__fmul_rn(x1, sc.x), __fmul_rn(x2, sc.y));
}

/* ---------------- k_pe = rope(ckv[:,512:576]) -------------------------- */
__global__ void kpe_kernel()
{
    const int l = blockIdx.x;
    const int i = threadIdx.x;           /* 32 pairs */
    const float* src = g_ckv + (long)l * (KVLORA + ROPED) + KVLORA + 2 * i;
    float2 sc = g_rope[l * 32 + i];
    float x1 = src[0], x2 = src[1];
    g_kpe[l * ROPED + 2 * i]     = __fsub_rn(__fmul_rn(x1, sc.y), __fmul_rn(x2, sc.x));
    g_kpe[l * ROPED + 2 * i + 1] = __fadd_rn(__fmul_rn(x1, sc.x), __fmul_rn(x2, sc.y));
}

/* ---------------- indexer scores: fp32 Kahan dots + fp64 head-sum ------ */
__global__ void __launch_bounds__(256) indexer_kernel()
{
    const int bs = blockIdx.x;
    const int bl = blockIdx.y;
    if (bs > bl) return;
    const int s0 = bs * 64;
    const int l0 = bl * 64;

    __shared__ float iqs[64][64];
    __shared__ float iks[64][64];

    const int tid = threadIdx.x;
    const int tm  = tid >> 4;
    const int tn  = tid & 15;

    double acc[4][4];
#pragma unroll
    for (int i = 0; i < 4; i++)
#pragma unroll
        for (int j = 0; j < 4; j++) acc[i][j] = 0.0;

    for (int h = 0; h < IHN; h++) {
        float ds[4][4], cc[4][4];
#pragma unroll
        for (int i = 0; i < 4; i++)
#pragma unroll
            for (int j = 0; j < 4; j++) { ds[i][j] = 0.f; cc[i][j] = 0.f; }

        for (int dc = 0; dc < IHDN; dc += 64) {
            __syncthreads();
#pragma unroll
            for (int t4 = 0; t4 < 4; t4++) {
                int id4 = tid + t4 * 256;
                int row = id4 >> 4;
                int c4  = (id4 & 15) << 2;
                float4 v = *(const float4*)(g_iq + (long)(l0 + row) * (IHN * IHDN)
                                            + h * IHDN + dc + c4);
                iqs[c4 + 0][row] = v.x; iqs[c4 + 1][row] = v.y;
                iqs[c4 + 2][row] = v.z; iqs[c4 + 3][row] = v.w;
                float4 u = *(const float4*)(g_ik + (long)(s0 + row) * IHDN + dc + c4);
                iks[c4 + 0][row] = u.x; iks[c4 + 1][row] = u.y;
                iks[c4 + 2][row] = u.z; iks[c4 + 3][row] = u.w;
            }
            __syncthreads();

#pragma unroll
            for (int g = 0; g < 4; g++) {
                float dt[4][4];
#pragma unroll
                for (int i = 0; i < 4; i++)
#pragma unroll
                    for (int j = 0; j < 4; j++) dt[i][j] = 0.f;

#pragma unroll
                for (int kk = g * 16; kk < g * 16 + 16; kk++) {
                    float4 a4 = *(const float4*)&iqs[kk][tm << 2];
                    float4 b4 = *(const float4*)&iks[kk][tn << 2];
                    float av[4] = {a4.x, a4.y, a4.z, a4.w};
                    float bv[4] = {b4.x, b4.y, b4.z, b4.w};
#pragma unroll
                    for (int i = 0; i < 4; i++)
#pragma unroll
                        for (int j = 0; j < 4; j++)
                            dt[i][j] = __fmaf_rn(av[i], bv[j], dt[i][j]);
                }
#pragma unroll
                for (int i = 0; i < 4; i++)
#pragma unroll
                    for (int j = 0; j < 4; j++) {
                        float y = __fsub_rn(dt[i][j], cc[i][j]);
                        float u = __fadd_rn(ds[i][j], y);
                        cc[i][j] = __fsub_rn(__fsub_rn(u, ds[i][j]), y);
                        ds[i][j] = u;
                    }
            }
        }

#pragma unroll
        for (int i = 0; i < 4; i++) {
            float wf = __fmul_rn(g_iw[(l0 + (tm << 2) + i) * IHN + h], IW_SCALE);
            double w = (double)wf;
#pragma unroll
            for (int j = 0; j < 4; j++) {
                double r = (double)ds[i][j];
                r = r > 0.0 ? r : 0.0;
                acc[i][j] += r * w;
            }
        }
    }

#pragma unroll
    for (int i = 0; i < 4; i++)
#pragma unroll
        for (int j = 0; j < 4; j++)
            g_isc[(long)(l0 + (tm << 2) + i) * LSEQ + s0 + (tn << 2) + j] =
                (float)acc[i][j];
}

/* ---------------- per-row top-256: stable bitonic (ties -> low index) -- */
__global__ void __launch_bounds__(1024) topk_kernel()
{
    const int l = blockIdx.x;
    const int t = threadIdx.x;
    __shared__ float sv[1024];
    __shared__ int   si[1024];

    sv[t] = (t <= l) ? g_isc[(long)l * LSEQ + t] : -INFINITY;
    si[t] = t;
    __syncthreads();

    for (int k = 2; k <= 1024; k <<= 1) {
        for (int j = k >> 1; j > 0; j >>= 1) {
            int p = t ^ j;
            if (p > t) {
                bool desc = ((t & k) == 0);
                float vt = sv[t], vp = sv[p];
                int   it = si[t], ip = si[p];
                bool t_lower = (vt < vp) || (vt == vp && it > ip);
                bool sw = desc ? t_lower : !t_lower;
                if (sw) {
                    sv[t] = vp; sv[p] = vt;
                    si[t] = ip; si[p] = it;
                }
            }
            __syncthreads();
        }
    }
    if (t < NTOPK) g_topk[l * NTOPK + t] = si[t];
}

/* ---------------- sparse attention over selected keys ------------------ */
__global__ void __launch_bounds__(128) attn_kernel()
{
    const int l = blockIdx.x;
    const int h = blockIdx.y;
    const int t = threadIdx.x;           /* 128 threads */
    __shared__ float q[QHD];
    __shared__ int   sidx[NTOPK];
    __shared__ float sc[NTOPK];
    __shared__ float red[4];
    __shared__ float smax, ssum;

    const long qbase = (long)l * (NH * QHD) + h * QHD;
    q[t] = g_q[qbase + t];
    if (t < 64) q[128 + t] = g_q[qbase + 128 + t] * ATT_SCALE;
    sidx[t]       = g_topk[l * NTOPK + t];
    sidx[t + 128] = g_topk[l * NTOPK + t + 128];
    __syncthreads();

    const int warp = t >> 5, lane = t & 31;

    for (int jj = 0; jj < 64; jj++) {
        int j = (warp << 6) + jj;
        int s = sidx[j];
        float r = -INFINITY;
        if (s <= l) {
            const float* kp = g_k + ((long)h * LSEQ + s) * NOPED;
            float dn = q[lane]      * kp[lane]
                     + q[lane + 32] * kp[lane + 32]
                     + q[lane + 64] * kp[lane + 64]
                     + q[lane + 96] * kp[lane + 96];
            const float* pp = g_kpe + s * ROPED;
            float dp = q[128 + lane] * pp[lane]
                     + q[160 + lane] * pp[lane + 32];
            float d = dn * ATT_SCALE + dp;
#pragma unroll
            for (int o = 16; o; o >>= 1) d += __shfl_xor_sync(0xffffffffu, d, o);
            r = d;
        }
        if (lane == 0) sc[j] = r;
    }
    __syncthreads();

    float m = fmaxf(sc[t], sc[t + 128]);
#pragma unroll
    for (int o = 16; o; o >>= 1) m = fmaxf(m, __shfl_xor_sync(0xffffffffu, m, o));
    if (lane == 0) red[warp] = m;
    __syncthreads();
    if (t == 0) smax = fmaxf(fmaxf(red[0], red[1]), fmaxf(red[2], red[3]));
    __syncthreads();
    float mx = smax;

    float p0 = expf(sc[t] - mx);
    float p1 = expf(sc[t + 128] - mx);
    float s = p0 + p1;
#pragma unroll
    for (int o = 16; o; o >>= 1) s += __shfl_xor_sync(0xffffffffu, s, o);
    if (lane == 0) red[warp] = s;
    __syncthreads();
    if (t == 0) ssum = red[0] + red[1] + red[2] + red[3];
    __syncthreads();
    float inv = 1.f / ssum;

    sc[t]       = p0 * inv;
    sc[t + 128] = p1 * inv;
    __syncthreads();

    float acc = 0.f;
    for (int j = 0; j < NTOPK; j++) {
        float p = sc[j];
        if (p != 0.f)
            acc += p * g_v[((long)h * LSEQ + sidx[j]) * VD + t];
    }
    g_ao[(long)l * (NH * VD) + h * VD + t] = acc;
}

/* ---------------------------- launcher --------------------------------- */
extern "C" void kernel_launch(void* const* d_in, const int* in_sizes, int n_in,
                              void* d_out, int out_size)
{
    (void)in_sizes; (void)n_in; (void)out_size;
    const float* x         = (const float*)d_in[0];
    const float* W_qa      = (const float*)d_in[2];
    const float* qa_ln_w   = (const float*)d_in[3];
    const float* W_qb      = (const float*)d_in[4];
    const float* W_kva     = (const float*)d_in[5];
    const float* kva_ln_w  = (const float*)d_in[6];
    const float* W_eq      = (const float*)d_in[7];
    const float* W_uo      = (const float*)d_in[8];
    const float* W_o       = (const float*)d_in[9];
    const float* idx_wqb   = (const float*)d_in[10];
    const float* idx_wk    = (const float*)d_in[11];
    const float* idx_kln_w = (const float*)d_in[12];
    const float* idx_kln_b = (const float*)d_in[13];
    const float* idx_wproj = (const float*)d_in[14];
    float* out = (float*)d_out;

    float *p_tmp, *p_qr, *p_q, *p_ckv, *p_kvlat, *p_iq, *p_ik, *p_iw, *p_k, *p_v, *p_ao;
    cudaGetSymbolAddress((void**)&p_tmp,   g_tmp);
    cudaGetSymbolAddress((void**)&p_qr,    g_qr);
    cudaGetSymbolAddress((void**)&p_q,     g_q);
    cudaGetSymbolAddress((void**)&p_ckv,   g_ckv);
    cudaGetSymbolAddress((void**)&p_kvlat, g_kvlat);
    cudaGetSymbolAddress((void**)&p_iq,    g_iq);
    cudaGetSymbolAddress((void**)&p_ik,    g_ik);
    cudaGetSymbolAddress((void**)&p_iw,    g_iw);
    cudaGetSymbolAddress((void**)&p_k,     g_k);
    cudaGetSymbolAddress((void**)&p_v,     g_v);
    cudaGetSymbolAddress((void**)&p_ao,    g_ao);

    rope_table_kernel<<<LSEQ, 32>>>();

    /* q path (tmp/qr feed the indexer -> Kahan exact) */
    gemm_kahan<true><<<dim3(QLORA / 64, LSEQ / 64), 256>>>(x, W_qa, p_tmp, LSEQ, QLORA, DMODEL);
    rmsnorm_kernel<<<LSEQ, 256>>>(p_tmp, qa_ln_w, p_qr, QLORA, QLORA, QLORA, 1e-6f);
    gemm_tc<true><<<dim3(NH * QHD / 128, LSEQ / 128), 256>>>(p_qr, W_qb, p_q, LSEQ, NH * QHD, QLORA, 0, 0);
    rope_apply_kernel<<<dim3(LSEQ, NH / 8), dim3(32, 8)>>>(p_q, NH * QHD, QHD, NOPED, NH);

    /* kv path */
    gemm_tc<true><<<dim3((KVLORA + ROPED + 127) / 128, LSEQ / 128), 256>>>(x, W_kva, p_ckv, LSEQ, KVLORA + ROPED, DMODEL, 0, 0);
    rmsnorm_kernel<<<LSEQ, 256>>>(p_ckv, kva_ln_w, p_kvlat, KVLORA, KVLORA + ROPED, KVLORA, 1e-6f);
    kpe_kernel<<<LSEQ, 32>>>();

    /* indexer path (score-exact -> Kahan) */
    gemm_kahan<true><<<dim3(IHN * IHDN / 64, LSEQ / 64), 256>>>(p_qr, idx_wqb, p_iq, LSEQ, IHN * IHDN, QLORA);
    rope_apply_kernel<<<dim3(LSEQ, IHN / 8), dim3(32, 8)>>>(p_iq, IHN * IHDN, IHDN, 0, IHN);
    gemm_kahan<true><<<dim3(IHDN / 64, LSEQ / 64), 256>>>(x, idx_wk, p_ik, LSEQ, IHDN, DMODEL);
    layernorm_ik_kernel<<<LSEQ, 128>>>(idx_kln_w, idx_kln_b);
    rope_apply_kernel<<<dim3(LSEQ, 1), dim3(32, 1)>>>(p_ik, IHDN, IHDN, 0, 1);
    gemm_kahan<true><<<dim3(IHN / 64, LSEQ / 64), 256>>>(x, idx_wproj, p_iw, LSEQ, IHN, DMODEL);

    indexer_kernel<<<dim3(LSEQ / 64, LSEQ / 64), 256>>>();
    topk_kernel<<<LSEQ, 1024>>>();

    /* k, v expansion (batched over heads, TC) */
    gemm_tc<false><<<dim3(NOPED / 128, LSEQ / 128, NH), 256>>>(p_kvlat, W_eq, p_k, LSEQ, NOPED, KVLORA,
                                                               (long)KVLORA * NOPED, (long)LSEQ * NOPED);
    gemm_tc<true><<<dim3(VD / 128, LSEQ / 128, NH), 256>>>(p_kvlat, W_uo, p_v, LSEQ, VD, KVLORA,
                                                           (long)VD * KVLORA, (long)LSEQ * VD);

    /* sparse attention */
    attn_kernel<<<dim3(LSEQ, NH), 128>>>();

    /* output projection (TC) */
    gemm_tc<true><<<dim3(DMODEL / 128, LSEQ / 128), 256>>>(p_ao, W_o, out, LSEQ, DMODEL, DMODEL, 0, 0);
}

// round 7
// speedup vs baseline: 24.6958x; 1.2940x over previous
#include <cuda_runtime.h>
#include <math.h>
#include <stdint.h>

#define LSEQ   1024
#define DMODEL 4096
#define NH     32
#define QLORA  1536
#define KVLORA 512
#define ROPED  64
#define NOPED  128
#define VD     128
#define QHD    192
#define IHN    64
#define IHDN   128
#define NTOPK  256

#define ATT_SCALE 0.07216878364870323f   /* 192^-0.5 */
#define IW_SCALE  0.011048543456039806f  /* (64*128)^-0.5 */

__device__ __forceinline__ uint32_t tf32bits(float x)
{
    uint32_t u;
    asm("cvt.rna.tf32.f32 %0, %1;" : "=r"(u) : "f"(x));
    return u;
}

/* Correctly-rounded rope trig: replicate JAX's f32 angle, then exact sincos. */
__device__ __forceinline__ void rope_trig(int l, int i, float* sn, float* cs)
{
    double invd = pow(10000.0, -(double)i * (1.0 / 32.0));
    float  invf = (float)invd;
    float  ang  = (float)l * invf;       /* f32 multiply, as in reference */
    double a    = (double)ang;
    *cs = (float)cos(a);
    *sn = (float)sin(a);
}

/* ---------------- scratch (device globals; no allocs allowed) ------------ */
__device__ float  g_tmp  [LSEQ * QLORA];
__device__ float  g_qr   [LSEQ * QLORA];
__device__ float  g_q    [LSEQ * NH * QHD];
__device__ float  g_ckv  [LSEQ * (KVLORA + ROPED)];
__device__ float  g_kvlat[LSEQ * KVLORA];
__device__ float  g_kpe  [LSEQ * ROPED];
__device__ float  g_iq   [LSEQ * IHN * IHDN];
__device__ float  g_ik   [LSEQ * IHDN];
__device__ float  g_iw   [LSEQ * IHN];
__device__ float  g_isc  [LSEQ * LSEQ];
__device__ int    g_topk [LSEQ * NTOPK];
__device__ float  g_k    [NH * LSEQ * NOPED];
__device__ float  g_v    [NH * LSEQ * VD];
__device__ float  g_ao   [LSEQ * NH * VD];
__device__ float2 g_rope [LSEQ * 32];
__device__ float  g_part [2 * LSEQ * QLORA];   /* split partials (max user) */

/* ================== TF32 tensor-core GEMM (non-score path) =============== */
#define TCPAD 4
template <bool TB>
__global__ void __launch_bounds__(256)
gemm_tc(const float* __restrict__ A, const float* __restrict__ B,
        float* __restrict__ C, int M, int N, int K,
        long strideB, long strideC)
{
    __shared__ uint32_t As[128][32 + TCPAD];
    __shared__ uint32_t Bs[128][32 + TCPAD];

    const float* Bp = B + (long)blockIdx.z * strideB;
    float*       Cp = C + (long)blockIdx.z * strideC;

    const int bm   = blockIdx.y * 128;
    const int bn   = blockIdx.x * 128;
    const int tid  = threadIdx.x;
    const int wid  = tid >> 5;
    const int lane = tid & 31;
    const int g    = lane >> 2;
    const int t4   = lane & 3;

    const int wm = (wid & 1) * 64;
    const int wn = (wid >> 1) * 32;

    float acc[4][4][4];
#pragma unroll
    for (int mi = 0; mi < 4; mi++)
#pragma unroll
        for (int ni = 0; ni < 4; ni++)
#pragma unroll
            for (int r = 0; r < 4; r++) acc[mi][ni][r] = 0.f;

    const int lr = tid >> 1;
    const int lc = (tid & 1) * 16;

    for (int k0 = 0; k0 < K; k0 += 32) {
#pragma unroll
        for (int q = 0; q < 4; q++) {
            float4 v = *(const float4*)(A + (long)(bm + lr) * K + k0 + lc + q * 4);
            *(uint4*)&As[lr][lc + q * 4] =
                make_uint4(tf32bits(v.x), tf32bits(v.y), tf32bits(v.z), tf32bits(v.w));
        }
        if (TB) {
            int row = bn + lr;
            if (row < N) {
#pragma unroll
                for (int q = 0; q < 4; q++) {
                    float4 v = *(const float4*)(Bp + (long)row * K + k0 + lc + q * 4);
                    *(uint4*)&Bs[lr][lc + q * 4] =
                        make_uint4(tf32bits(v.x), tf32bits(v.y), tf32bits(v.z), tf32bits(v.w));
                }
            } else {
#pragma unroll
                for (int q = 0; q < 4; q++)
                    *(uint4*)&Bs[lr][lc + q * 4] = make_uint4(0, 0, 0, 0);
            }
        } else {
            int k  = tid >> 3;
            int nb = (tid & 7) * 16;
#pragma unroll
            for (int q = 0; q < 16; q += 4) {
                int n = bn + nb + q;
                if (n + 3 < N) {
                    float4 v = *(const float4*)(Bp + (long)(k0 + k) * N + n);
                    Bs[nb + q + 0][k] = tf32bits(v.x);
                    Bs[nb + q + 1][k] = tf32bits(v.y);
                    Bs[nb + q + 2][k] = tf32bits(v.z);
                    Bs[nb + q + 3][k] = tf32bits(v.w);
                } else {
#pragma unroll
                    for (int e = 0; e < 4; e++) {
                        float f = (n + e < N) ? Bp[(long)(k0 + k) * N + n + e] : 0.f;
                        Bs[nb + q + e][k] = tf32bits(f);
                    }
                }
            }
        }
        __syncthreads();

#pragma unroll
        for (int ks = 0; ks < 4; ks++) {
            const int kb = ks * 8;
            uint32_t af[4][4];
#pragma unroll
            for (int mi = 0; mi < 4; mi++) {
                int r = wm + mi * 16;
                af[mi][0] = As[r + g][kb + t4];
                af[mi][1] = As[r + g + 8][kb + t4];
                af[mi][2] = As[r + g][kb + t4 + 4];
                af[mi][3] = As[r + g + 8][kb + t4 + 4];
            }
            uint32_t bf[4][2];
#pragma unroll
            for (int ni = 0; ni < 4; ni++) {
                int c = wn + ni * 8;
                bf[ni][0] = Bs[c + g][kb + t4];
                bf[ni][1] = Bs[c + g][kb + t4 + 4];
            }
#pragma unroll
            for (int mi = 0; mi < 4; mi++)
#pragma unroll
                for (int ni = 0; ni < 4; ni++) {
                    asm volatile(
                        "mma.sync.aligned.m16n8k8.row.col.f32.tf32.tf32.f32 "
                        "{%0,%1,%2,%3}, {%4,%5,%6,%7}, {%8,%9}, {%0,%1,%2,%3};\n"
                        : "+f"(acc[mi][ni][0]), "+f"(acc[mi][ni][1]),
                          "+f"(acc[mi][ni][2]), "+f"(acc[mi][ni][3])
                        : "r"(af[mi][0]), "r"(af[mi][1]),
                          "r"(af[mi][2]), "r"(af[mi][3]),
                          "r"(bf[ni][0]), "r"(bf[ni][1]));
                }
        }
        __syncthreads();
    }

#pragma unroll
    for (int mi = 0; mi < 4; mi++) {
#pragma unroll
        for (int ni = 0; ni < 4; ni++) {
            int r0 = bm + wm + mi * 16 + g;
            int c0 = bn + wn + ni * 8 + t4 * 2;
            if (c0 < N) {
                Cp[(long)r0 * N + c0] = acc[mi][ni][0];
                if (c0 + 1 < N) Cp[(long)r0 * N + c0 + 1] = acc[mi][ni][1];
                Cp[(long)(r0 + 8) * N + c0] = acc[mi][ni][2];
                if (c0 + 1 < N) Cp[(long)(r0 + 8) * N + c0 + 1] = acc[mi][ni][3];
            }
        }
    }
}

/* ============ Kahan fp32 GEMM, 128x64 tile, 8x4 microtile, K-split ======= */
/* C = A * B^T. A [M,K], B [N,K] row-major. M mult of 128, N mult of 64.     */
/* Per 16-k: fp32 FMA block, Kahan merge (same numerics as prior pass).      */
/* SPLIT>1: block z handles K-chunk z, writes partial to C + z*M*N.          */
template <int SPLIT>
__global__ void __launch_bounds__(256)
gemm_k128(const float* __restrict__ A, const float* __restrict__ B,
          float* __restrict__ C, int M, int N, int K)
{
    __shared__ float As[16][128];
    __shared__ float Bs[16][64];

    const int bm    = blockIdx.y * 128;
    const int bn    = blockIdx.x * 64;
    const int kLen  = K / SPLIT;
    const int kBase = blockIdx.z * kLen;
    float* Cp = C + (long)blockIdx.z * M * N;

    const int tid = threadIdx.x;
    const int tm  = tid >> 4;           /* 0..15 : rows tm*8..+8 */
    const int tn  = tid & 15;           /* 0..15 : cols tn*4..+4 */

    const int ar = tid >> 1;            /* 0..127 */
    const int ac = (tid & 1) << 3;      /* 0 or 8 */
    const int br = tid >> 2;            /* 0..63  */
    const int bc = (tid & 3) << 2;      /* 0,4,8,12 */

    float s_[8][4], c_[8][4];
#pragma unroll
    for (int i = 0; i < 8; i++)
#pragma unroll
        for (int j = 0; j < 4; j++) { s_[i][j] = 0.f; c_[i][j] = 0.f; }

    for (int k0 = kBase; k0 < kBase + kLen; k0 += 16) {
        float4 a0 = *(const float4*)(A + (long)(bm + ar) * K + k0 + ac);
        float4 a1 = *(const float4*)(A + (long)(bm + ar) * K + k0 + ac + 4);
        As[ac + 0][ar] = a0.x; As[ac + 1][ar] = a0.y;
        As[ac + 2][ar] = a0.z; As[ac + 3][ar] = a0.w;
        As[ac + 4][ar] = a1.x; As[ac + 5][ar] = a1.y;
        As[ac + 6][ar] = a1.z; As[ac + 7][ar] = a1.w;

        float4 b0 = *(const float4*)(B + (long)(bn + br) * K + k0 + bc);
        Bs[bc + 0][br] = b0.x; Bs[bc + 1][br] = b0.y;
        Bs[bc + 2][br] = b0.z; Bs[bc + 3][br] = b0.w;
        __syncthreads();

        float t_[8][4];
#pragma unroll
        for (int i = 0; i < 8; i++)
#pragma unroll
            for (int j = 0; j < 4; j++) t_[i][j] = 0.f;

#pragma unroll
        for (int kk = 0; kk < 16; kk++) {
            float4 va0 = *(const float4*)&As[kk][tm << 3];
            float4 va1 = *(const float4*)&As[kk][(tm << 3) + 4];
            float4 vb  = *(const float4*)&Bs[kk][tn << 2];
            float av[8] = {va0.x, va0.y, va0.z, va0.w, va1.x, va1.y, va1.z, va1.w};
            float bv[4] = {vb.x, vb.y, vb.z, vb.w};
#pragma unroll
            for (int i = 0; i < 8; i++)
#pragma unroll
                for (int j = 0; j < 4; j++)
                    t_[i][j] = __fmaf_rn(av[i], bv[j], t_[i][j]);
        }
#pragma unroll
        for (int i = 0; i < 8; i++)
#pragma unroll
            for (int j = 0; j < 4; j++) {
                float y = __fsub_rn(t_[i][j], c_[i][j]);
                float u = __fadd_rn(s_[i][j], y);
                c_[i][j] = __fsub_rn(__fsub_rn(u, s_[i][j]), y);
                s_[i][j] = u;
            }
        __syncthreads();
    }

#pragma unroll
    for (int i = 0; i < 8; i++) {
        float4 r;
        r.x = s_[i][0]; r.y = s_[i][1]; r.z = s_[i][2]; r.w = s_[i][3];
        *(float4*)(Cp + (long)(bm + (tm << 3) + i) * N + bn + (tn << 2)) = r;
    }
}

/* ---------------- combine K-split partials ------------------------------ */
__global__ void combine_kernel(const float* __restrict__ part,
                               float* __restrict__ dst, int MN, int S)
{
    int i = blockIdx.x * 256 + threadIdx.x;
    if (i < MN) {
        float s = part[i];
        for (int k = 1; k < S; k++) s = __fadd_rn(s, part[(long)k * MN + i]);
        dst[i] = s;
    }
}

/* ---------------- rmsnorm over a row (double-precision stats) ---------- */
__global__ void rmsnorm_kernel(const float* __restrict__ in,
                               const float* __restrict__ w,
                               float* __restrict__ out,
                               int cols, int inStride, int outStride, float eps)
{
    const int l = blockIdx.x;
    const int t = threadIdx.x;
    __shared__ double red[8];
    __shared__ float rshared;

    double ss = 0.0;
    for (int c = t; c < cols; c += 256) {
        double v = (double)in[(long)l * inStride + c];
        ss += v * v;
    }
#pragma unroll
    for (int o = 16; o; o >>= 1) ss += __shfl_xor_sync(0xffffffffu, ss, o);
    if ((t & 31) == 0) red[t >> 5] = ss;
    __syncthreads();
    if (t == 0) {
        double s = 0.0;
        for (int i = 0; i < 8; i++) s += red[i];
        rshared = (float)rsqrt(s / (double)cols + (double)eps);
    }
    __syncthreads();
    float r = rshared;
    for (int c = t; c < cols; c += 256)
        out[(long)l * outStride + c] = in[(long)l * inStride + c] * r * w[c];
}

/* ---------------- layernorm (in-place) on g_ik, cols=128, fp64 stats --- */
__global__ void layernorm_ik_kernel(const float* __restrict__ w,
                                    const float* __restrict__ b)
{
    const int l = blockIdx.x;
    const int t = threadIdx.x;
    __shared__ double red[4];
    __shared__ double stat;

    float v = g_ik[l * IHDN + t];

    double s = (double)v;
#pragma unroll
    for (int o = 16; o; o >>= 1) s += __shfl_xor_sync(0xffffffffu, s, o);
    if ((t & 31) == 0) red[t >> 5] = s;
    __syncthreads();
    if (t == 0) stat = (red[0] + red[1] + red[2] + red[3]) * (1.0 / 128.0);
    __syncthreads();
    double mu = stat;
    double d  = (double)v - mu;

    double s2 = d * d;
#pragma unroll
    for (int o = 16; o; o >>= 1) s2 += __shfl_xor_sync(0xffffffffu, s2, o);
    __syncthreads();
    if ((t & 31) == 0) red[t >> 5] = s2;
    __syncthreads();
    if (t == 0) stat = (red[0] + red[1] + red[2] + red[3]) * (1.0 / 128.0);
    __syncthreads();
    double var = stat;

    g_ik[l * IHDN + t] = (float)(d * rsqrt(var + 1e-5)) * w[t] + b[t];
}

/* ---------------- rope table (exact trig, computed once) --------------- */
__global__ void rope_table_kernel()
{
    const int l = blockIdx.x;
    const int i = threadIdx.x;
    float sn, cs;
    rope_trig(l, i, &sn, &cs);
    g_rope[l * 32 + i] = make_float2(sn, cs);
}

/* ---------------- rope application (table lookup) ---------------------- */
__global__ void rope_apply_kernel(float* data, int rowStride,
                                  int chunkStride, int off, int nchunks)
{
    const int l = blockIdx.x;
    const int c = blockIdx.y * blockDim.y + threadIdx.y;
    if (c >= nchunks) return;
    const int i = threadIdx.x;
    float2 sc = g_rope[l * 32 + i];
    float* p = data + (long)l * rowStride + c * chunkStride + off + 2 * i;
    float x1 = p[0], x2 = p[1];
    p[0] = __fsub_rn(__fmul_rn(x1, sc.y), __fmul_rn(x2, sc.x));
    p[1] = __fadd_rn(__fmul_rn(x1, sc.x), __fmul_rn(x2, sc.y));
}

/* ---------------- k_pe = rope(ckv[:,512:576]) -------------------------- */
__global__ void kpe_kernel()
{
    const int l = blockIdx.x;
    const int i = threadIdx.x;
    const float* src = g_ckv + (long)l * (KVLORA + ROPED) + KVLORA + 2 * i;
    float2 sc = g_rope[l * 32 + i];
    float x1 = src[0], x2 = src[1];
    g_kpe[l * ROPED + 2 * i]     = __fsub_rn(__fmul_rn(x1, sc.y), __fmul_rn(x2, sc.x));
    g_kpe[l * ROPED + 2 * i + 1] = __fadd_rn(__fmul_rn(x1, sc.x), __fmul_rn(x2, sc.y));
}

/* ------- indexer: 128(l) x 64(s) tiles, 8x4 microtile, 2 head-groups ---- */
/* partial score for head-group z written to g_part[z]; combined after.     */
__global__ void __launch_bounds__(256) indexer_kernel()
{
    const int bs = blockIdx.x;            /* s tile (64)   */
    const int bl = blockIdx.y;            /* l tile (128)  */
    const int hz = blockIdx.z;            /* head group    */
    const int s0 = bs * 64;
    const int l0 = bl * 128;
    if (s0 > l0 + 127) return;

    __shared__ float iqs[64][128];        /* [d][l] */
    __shared__ float iks[64][64];         /* [d][s] */

    const int tid = threadIdx.x;
    const int tm  = tid >> 4;
    const int tn  = tid & 15;

    float sa[8][4], ca[8][4];
#pragma unroll
    for (int i = 0; i < 8; i++)
#pragma unroll
        for (int j = 0; j < 4; j++) { sa[i][j] = 0.f; ca[i][j] = 0.f; }

    const int qrow = tid >> 1;            /* l 0..127 */
    const int qdb  = (tid & 1) * 32;
    const int krow = tid >> 2;            /* s 0..63  */
    const int kdb  = (tid & 3) * 16;

    for (int h = hz * 32; h < hz * 32 + 32; h++) {
        float sd[8][4], cd[8][4];
#pragma unroll
        for (int i = 0; i < 8; i++)
#pragma unroll
            for (int j = 0; j < 4; j++) { sd[i][j] = 0.f; cd[i][j] = 0.f; }

        for (int dc = 0; dc < IHDN; dc += 64) {
            __syncthreads();
            {
                const float* src = g_iq + (long)(l0 + qrow) * (IHN * IHDN)
                                   + h * IHDN + dc + qdb;
#pragma unroll
                for (int e = 0; e < 8; e++) {
                    float4 v = *(const float4*)(src + e * 4);
                    iqs[qdb + e * 4 + 0][qrow] = v.x;
                    iqs[qdb + e * 4 + 1][qrow] = v.y;
                    iqs[qdb + e * 4 + 2][qrow] = v.z;
                    iqs[qdb + e * 4 + 3][qrow] = v.w;
                }
                const float* src2 = g_ik + (long)(s0 + krow) * IHDN + dc + kdb;
#pragma unroll
                for (int e = 0; e < 4; e++) {
                    float4 u = *(const float4*)(src2 + e * 4);
                    iks[kdb + e * 4 + 0][krow] = u.x;
                    iks[kdb + e * 4 + 1][krow] = u.y;
                    iks[kdb + e * 4 + 2][krow] = u.z;
                    iks[kdb + e * 4 + 3][krow] = u.w;
                }
            }
            __syncthreads();

#pragma unroll
            for (int g4 = 0; g4 < 4; g4++) {
                float td[8][4];
#pragma unroll
                for (int i = 0; i < 8; i++)
#pragma unroll
                    for (int j = 0; j < 4; j++) td[i][j] = 0.f;

#pragma unroll
                for (int kk = g4 * 16; kk < g4 * 16 + 16; kk++) {
                    float4 va0 = *(const float4*)&iqs[kk][tm << 3];
                    float4 va1 = *(const float4*)&iqs[kk][(tm << 3) + 4];
                    float4 vb  = *(const float4*)&iks[kk][tn << 2];
                    float av[8] = {va0.x, va0.y, va0.z, va0.w,
                                   va1.x, va1.y, va1.z, va1.w};
                    float bv[4] = {vb.x, vb.y, vb.z, vb.w};
#pragma unroll
                    for (int i = 0; i < 8; i++)
#pragma unroll
                        for (int j = 0; j < 4; j++)
                            td[i][j] = __fmaf_rn(av[i], bv[j], td[i][j]);
                }
#pragma unroll
                for (int i = 0; i < 8; i++)
#pragma unroll
                    for (int j = 0; j < 4; j++) {
                        float y = __fsub_rn(td[i][j], cd[i][j]);
                        float u = __fadd_rn(sd[i][j], y);
                        cd[i][j] = __fsub_rn(__fsub_rn(u, sd[i][j]), y);
                        sd[i][j] = u;
                    }
            }
        }

        /* head-sum: relu(dot)*iw, Kahan-accumulated */
#pragma unroll
        for (int i = 0; i < 8; i++) {
            float wf = __fmul_rn(g_iw[(l0 + (tm << 3) + i) * IHN + h], IW_SCALE);
#pragma unroll
            for (int j = 0; j < 4; j++) {
                float rv = __fmul_rn(fmaxf(sd[i][j], 0.f), wf);
                float y = __fsub_rn(rv, ca[i][j]);
                float u = __fadd_rn(sa[i][j], y);
                ca[i][j] = __fsub_rn(__fsub_rn(u, sa[i][j]), y);
                sa[i][j] = u;
            }
        }
    }

#pragma unroll
    for (int i = 0; i < 8; i++) {
        float4 r;
        r.x = sa[i][0]; r.y = sa[i][1]; r.z = sa[i][2]; r.w = sa[i][3];
        *(float4*)(g_part + (long)hz * (LSEQ * LSEQ)
                   + (long)(l0 + (tm << 3) + i) * LSEQ + s0 + (tn << 2)) = r;
    }
}

/* ---------------- per-row top-256: stable bitonic (ties -> low index) -- */
__global__ void __launch_bounds__(1024) topk_kernel()
{
    const int l = blockIdx.x;
    const int t = threadIdx.x;
    __shared__ float sv[1024];
    __shared__ int   si[1024];

    sv[t] = (t <= l) ? g_isc[(long)l * LSEQ + t] : -INFINITY;
    si[t] = t;
    __syncthreads();

    for (int k = 2; k <= 1024; k <<= 1) {
        for (int j = k >> 1; j > 0; j >>= 1) {
            int p = t ^ j;
            if (p > t) {
                bool desc = ((t & k) == 0);
                float vt = sv[t], vp = sv[p];
                int   it = si[t], ip = si[p];
                bool t_lower = (vt < vp) || (vt == vp && it > ip);
                bool sw = desc ? t_lower : !t_lower;
                if (sw) {
                    sv[t] = vp; sv[p] = vt;
                    si[t] = ip; si[p] = it;
                }
            }
            __syncthreads();
        }
    }
    if (t < NTOPK) g_topk[l * NTOPK + t] = si[t];
}

/* ---------------- sparse attention over selected keys ------------------ */
__global__ void __launch_bounds__(128) attn_kernel()
{
    const int l = blockIdx.x;
    const int h = blockIdx.y;
    const int t = threadIdx.x;
    __shared__ float q[QHD];
    __shared__ int   sidx[NTOPK];
    __shared__ float sc[NTOPK];
    __shared__ float red[4];
    __shared__ float smax, ssum;

    const long qbase = (long)l * (NH * QHD) + h * QHD;
    q[t] = g_q[qbase + t];
    if (t < 64) q[128 + t] = g_q[qbase + 128 + t] * ATT_SCALE;
    sidx[t]       = g_topk[l * NTOPK + t];
    sidx[t + 128] = g_topk[l * NTOPK + t + 128];
    __syncthreads();

    const int warp = t >> 5, lane = t & 31;

    for (int jj = 0; jj < 64; jj++) {
        int j = (warp << 6) + jj;
        int s = sidx[j];
        float r = -INFINITY;
        if (s <= l) {
            const float* kp = g_k + ((long)h * LSEQ + s) * NOPED;
            float dn = q[lane]      * kp[lane]
                     + q[lane + 32] * kp[lane + 32]
                     + q[lane + 64] * kp[lane + 64]
                     + q[lane + 96] * kp[lane + 96];
            const float* pp = g_kpe + s * ROPED;
            float dp = q[128 + lane] * pp[lane]
                     + q[160 + lane] * pp[lane + 32];
            float d = dn * ATT_SCALE + dp;
#pragma unroll
            for (int o = 16; o; o >>= 1) d += __shfl_xor_sync(0xffffffffu, d, o);
            r = d;
        }
        if (lane == 0) sc[j] = r;
    }
    __syncthreads();

    float m = fmaxf(sc[t], sc[t + 128]);
#pragma unroll
    for (int o = 16; o; o >>= 1) m = fmaxf(m, __shfl_xor_sync(0xffffffffu, m, o));
    if (lane == 0) red[warp] = m;
    __syncthreads();
    if (t == 0) smax = fmaxf(fmaxf(red[0], red[1]), fmaxf(red[2], red[3]));
    __syncthreads();
    float mx = smax;

    float p0 = expf(sc[t] - mx);
    float p1 = expf(sc[t + 128] - mx);
    float s = p0 + p1;
#pragma unroll
    for (int o = 16; o; o >>= 1) s += __shfl_xor_sync(0xffffffffu, s, o);
    if (lane == 0) red[warp] = s;
    __syncthreads();
    if (t == 0) ssum = red[0] + red[1] + red[2] + red[3];
    __syncthreads();
    float inv = 1.f / ssum;

    sc[t]       = p0 * inv;
    sc[t + 128] = p1 * inv;
    __syncthreads();

    float acc = 0.f;
    for (int j = 0; j < NTOPK; j++) {
        float p = sc[j];
        if (p != 0.f)
            acc += p * g_v[((long)h * LSEQ + sidx[j]) * VD + t];
    }
    g_ao[(long)l * (NH * VD) + h * VD + t] = acc;
}

/* ---------------------------- launcher --------------------------------- */
extern "C" void kernel_launch(void* const* d_in, const int* in_sizes, int n_in,
                              void* d_out, int out_size)
{
    (void)in_sizes; (void)n_in; (void)out_size;
    const float* x         = (const float*)d_in[0];
    const float* W_qa      = (const float*)d_in[2];
    const float* qa_ln_w   = (const float*)d_in[3];
    const float* W_qb      = (const float*)d_in[4];
    const float* W_kva     = (const float*)d_in[5];
    const float* kva_ln_w  = (const float*)d_in[6];
    const float* W_eq      = (const float*)d_in[7];
    const float* W_uo      = (const float*)d_in[8];
    const float* W_o       = (const float*)d_in[9];
    const float* idx_wqb   = (const float*)d_in[10];
    const float* idx_wk    = (const float*)d_in[11];
    const float* idx_kln_w = (const float*)d_in[12];
    const float* idx_kln_b = (const float*)d_in[13];
    const float* idx_wproj = (const float*)d_in[14];
    float* out = (float*)d_out;

    float *p_tmp, *p_qr, *p_q, *p_ckv, *p_kvlat, *p_iq, *p_ik, *p_iw, *p_k, *p_v, *p_ao, *p_part, *p_isc;
    cudaGetSymbolAddress((void**)&p_tmp,   g_tmp);
    cudaGetSymbolAddress((void**)&p_qr,    g_qr);
    cudaGetSymbolAddress((void**)&p_q,     g_q);
    cudaGetSymbolAddress((void**)&p_ckv,   g_ckv);
    cudaGetSymbolAddress((void**)&p_kvlat, g_kvlat);
    cudaGetSymbolAddress((void**)&p_iq,    g_iq);
    cudaGetSymbolAddress((void**)&p_ik,    g_ik);
    cudaGetSymbolAddress((void**)&p_iw,    g_iw);
    cudaGetSymbolAddress((void**)&p_k,     g_k);
    cudaGetSymbolAddress((void**)&p_v,     g_v);
    cudaGetSymbolAddress((void**)&p_ao,    g_ao);
    cudaGetSymbolAddress((void**)&p_part,  g_part);
    cudaGetSymbolAddress((void**)&p_isc,   g_isc);

    rope_table_kernel<<<LSEQ, 32>>>();

    /* q path (tmp/qr feed the indexer -> Kahan exact) */
    gemm_k128<2><<<dim3(QLORA / 64, LSEQ / 128, 2), 256>>>(x, W_qa, p_part, LSEQ, QLORA, DMODEL);
    combine_kernel<<<(LSEQ * QLORA + 255) / 256, 256>>>(p_part, p_tmp, LSEQ * QLORA, 2);
    rmsnorm_kernel<<<LSEQ, 256>>>(p_tmp, qa_ln_w, p_qr, QLORA, QLORA, QLORA, 1e-6f);
    gemm_tc<true><<<dim3(NH * QHD / 128, LSEQ / 128), 256>>>(p_qr, W_qb, p_q, LSEQ, NH * QHD, QLORA, 0, 0);
    rope_apply_kernel<<<dim3(LSEQ, NH / 8), dim3(32, 8)>>>(p_q, NH * QHD, QHD, NOPED, NH);

    /* kv path */
    gemm_tc<true><<<dim3((KVLORA + ROPED + 127) / 128, LSEQ / 128), 256>>>(x, W_kva, p_ckv, LSEQ, KVLORA + ROPED, DMODEL, 0, 0);
    rmsnorm_kernel<<<LSEQ, 256>>>(p_ckv, kva_ln_w, p_kvlat, KVLORA, KVLORA + ROPED, KVLORA, 1e-6f);
    kpe_kernel<<<LSEQ, 32>>>();

    /* indexer path (score-exact -> Kahan) */
    gemm_k128<1><<<dim3(IHN * IHDN / 64, LSEQ / 128, 1), 256>>>(p_qr, idx_wqb, p_iq, LSEQ, IHN * IHDN, QLORA);
    rope_apply_kernel<<<dim3(LSEQ, IHN / 8), dim3(32, 8)>>>(p_iq, IHN * IHDN, IHDN, 0, IHN);
    gemm_k128<8><<<dim3(IHDN / 64, LSEQ / 128, 8), 256>>>(x, idx_wk, p_part, LSEQ, IHDN, DMODEL);
    combine_kernel<<<(LSEQ * IHDN + 255) / 256, 256>>>(p_part, p_ik, LSEQ * IHDN, 8);
    layernorm_ik_kernel<<<LSEQ, 128>>>(idx_kln_w, idx_kln_b);
    rope_apply_kernel<<<dim3(LSEQ, 1), dim3(32, 1)>>>(p_ik, IHDN, IHDN, 0, 1);
    gemm_k128<8><<<dim3(IHN / 64, LSEQ / 128, 8), 256>>>(x, idx_wproj, p_part, LSEQ, IHN, DMODEL);
    combine_kernel<<<(LSEQ * IHN + 255) / 256, 256>>>(p_part, p_iw, LSEQ * IHN, 8);

    indexer_kernel<<<dim3(LSEQ / 64, LSEQ / 128, 2), 256>>>();
    combine_kernel<<<(LSEQ * LSEQ + 255) / 256, 256>>>(p_part, p_isc, LSEQ * LSEQ, 2);
    topk_kernel<<<LSEQ, 1024>>>();

    /* k, v expansion (batched over heads, TC) */
    gemm_tc<false><<<dim3(NOPED / 128, LSEQ / 128, NH), 256>>>(p_kvlat, W_eq, p_k, LSEQ, NOPED, KVLORA,
                                                               (long)KVLORA * NOPED, (long)LSEQ * NOPED);
    gemm_tc<true><<<dim3(VD / 128, LSEQ / 128, NH), 256>>>(p_kvlat, W_uo, p_v, LSEQ, VD, KVLORA,
                                                           (long)VD * KVLORA, (long)LSEQ * VD);

    /* sparse attention */
    attn_kernel<<<dim3(LSEQ, NH), 128>>>();

    /* output projection (TC) */
    gemm_tc<true><<<dim3(DMODEL / 128, LSEQ / 128), 256>>>(p_ao, W_o, out, LSEQ, DMODEL, DMODEL, 0, 0);
}